// round 14
// baseline (speedup 1.0000x reference)
#include <cuda_runtime.h>
#include <cuda_fp16.h>
#include <math.h>
#include <stdint.h>

#define T_  64
#define B_  64
#define S_  128
#define E_  512
#define H_  1024
#define EH_ 1536
#define BH_ (B_*H_)
#define TBH_ ((size_t)T_*B_*H_)
#define NCTA 256
#define NTHR 256

// ---------------- scratch (device globals; zero-init) ----------------
__device__ __align__(16) __half g_wih0h[(size_t)4*H_*EH_];
__device__ __align__(16) __half g_whh0h[(size_t)4*H_*H_];
__device__ __align__(16) __half g_wih1h[(size_t)4*H_*H_];
__device__ __align__(16) __half g_whh1h[(size_t)4*H_*H_];
__device__ __align__(16) __half g_wah[(size_t)H_*H_];
__device__ __align__(16) __half g_wouth[(size_t)H_*2*H_];
__device__ __align__(16) __half g_inph[(size_t)T_*B_*E_];
__device__ __align__(16) __half g_ctxh[(size_t)S_*B_*H_];
__device__ __align__(16) __half g_ctxwh[(size_t)S_*B_*H_];   // ctx @ WoutL^T (half)
__device__ __align__(16) __half g_hb0h[2*BH_];
__device__ __align__(16) __half g_hb1h[2*BH_];
__device__ __align__(16) __half g_feedh[BH_];
__device__ __align__(16) __half g_zerosh[BH_];   // never written -> 0
__device__ __align__(16) float g_hraw0[BH_];
__device__ __align__(16) float g_hraw1[BH_];
__device__ __align__(16) float g_cb0[BH_];
__device__ __align__(16) float g_cb1[BH_];
__device__ __align__(16) float g_q[BH_];
__device__ __align__(16) float g_oh1[BH_];
__device__ __align__(16) float g_scores[B_*S_];
__device__ __align__(16) float g_pre[(size_t)T_*B_*4*H_];   // inp proj (fp32)
__device__ __align__(16) float g_part[(size_t)NCTA*8192];   // split-K partials

// epoch counters (zeroed by prep_state every call)
__device__ unsigned long long c_l0[32], c_l1[32], c_q[8], c_oh[8], c_at[64];
__device__ unsigned long long c_p0, c_p1, c_p2q, c_p2o, c_p4;

__device__ __forceinline__ float sigf(float x) { return 1.f / (1.f + expf(-x)); }

__device__ __forceinline__ void cp16(void* dst, const void* src) {
    unsigned s = (unsigned)__cvta_generic_to_shared(dst);
    asm volatile("cp.async.cg.shared.global [%0], [%1], 16;\n" :: "r"(s), "l"(src));
}

__device__ __forceinline__ void mma16(float* c, const uint32_t* a, const uint32_t* b) {
    asm volatile(
        "mma.sync.aligned.m16n8k16.row.col.f32.f16.f16.f32 "
        "{%0,%1,%2,%3}, {%4,%5,%6,%7}, {%8,%9}, {%0,%1,%2,%3};\n"
        : "+f"(c[0]), "+f"(c[1]), "+f"(c[2]), "+f"(c[3])
        : "r"(a[0]), "r"(a[1]), "r"(a[2]), "r"(a[3]), "r"(b[0]), "r"(b[1]));
}

__device__ __forceinline__ void arrive(unsigned long long* c) {
    __threadfence();
    __syncthreads();
    if (threadIdx.x == 0) atomicAdd(c, 1ULL);
}
__device__ __forceinline__ void wait_ge(unsigned long long* c, unsigned long long tgt) {
    if (threadIdx.x == 0) {
        unsigned long long v;
        do {
            asm volatile("ld.acquire.gpu.u64 %0, [%1];" : "=l"(v) : "l"(c));
        } while (v < tgt);
    }
    __syncthreads();
}

// ---------------- prep kernels (vectorized) ----------------
__global__ __launch_bounds__(512) void prep_weights(
    const float* __restrict__ wih0, const float* __restrict__ whh0,
    const float* __restrict__ wih1, const float* __restrict__ whh1,
    const float* __restrict__ wa,   const float* __restrict__ wout) {
    const size_t n0 = (size_t)4 * H_ * EH_;
    const size_t n1 = (size_t)4 * H_ * H_;
    const size_t n2 = (size_t)H_ * H_;
    const size_t n3 = (size_t)H_ * 2 * H_;
    const size_t tot4 = (n0 + 3 * n1 + n2 + n3) >> 2;
    for (size_t i4 = (size_t)blockIdx.x * blockDim.x + threadIdx.x; i4 < tot4;
         i4 += (size_t)gridDim.x * blockDim.x) {
        size_t j = i4 << 2; const float* s; __half* d;
        if (j < n0) { s = wih0 + j; d = g_wih0h + j; }
        else { j -= n0;
        if (j < n1) { s = whh0 + j; d = g_whh0h + j; }
        else { j -= n1;
        if (j < n1) { s = wih1 + j; d = g_wih1h + j; }
        else { j -= n1;
        if (j < n1) { s = whh1 + j; d = g_whh1h + j; }
        else { j -= n1;
        if (j < n2) { s = wa + j;   d = g_wah + j; }
        else { j -= n2; s = wout + j; d = g_wouth + j; } } } } }
        float4 v = *(const float4*)s;
        *(__half2*)(d)     = __floats2half2_rn(v.x, v.y);
        *(__half2*)(d + 2) = __floats2half2_rn(v.z, v.w);
    }
}

__global__ __launch_bounds__(512) void prep_state(const float* __restrict__ inp,
                                                  const float* __restrict__ ctx,
                                                  const float* __restrict__ h0,
                                                  const float* __restrict__ c0) {
    if (blockIdx.x == 0) {
        int t = threadIdx.x;
        if (t < 32) { c_l0[t] = 0; c_l1[t] = 0; }
        if (t < 8)  { c_q[t] = 0; c_oh[t] = 0; }
        if (t < 64) c_at[t] = 0;
        if (t == 0) { c_p0 = 0; c_p1 = 0; c_p2q = 0; c_p2o = 0; c_p4 = 0; }
    }
    const size_t ninp = (size_t)T_ * B_ * E_;
    const size_t nctx = (size_t)S_ * B_ * H_;
    const size_t tot4 = (ninp + nctx + 2 * BH_) >> 2;
    for (size_t i4 = (size_t)blockIdx.x * blockDim.x + threadIdx.x; i4 < tot4;
         i4 += (size_t)gridDim.x * blockDim.x) {
        size_t j = i4 << 2;
        if (j < ninp) {
            float4 v = *(const float4*)(inp + j);
            *(__half2*)(g_inph + j)     = __floats2half2_rn(v.x, v.y);
            *(__half2*)(g_inph + j + 2) = __floats2half2_rn(v.z, v.w);
            continue;
        }
        j -= ninp;
        if (j < nctx) {
            float4 v = *(const float4*)(ctx + j);
            *(__half2*)(g_ctxh + j)     = __floats2half2_rn(v.x, v.y);
            *(__half2*)(g_ctxh + j + 2) = __floats2half2_rn(v.z, v.w);
            continue;
        }
        j -= nctx;
        float4 hv = *(const float4*)(h0 + j);
        float4 cv = *(const float4*)(c0 + j);
        __half* hd; float* cd; size_t jj;
        if (j < BH_) { jj = j; hd = g_hb0h; cd = g_cb0; }
        else { jj = j - BH_; hd = g_hb1h; cd = g_cb1; }
        *(__half2*)(hd + jj)     = __floats2half2_rn(hv.x, hv.y);
        *(__half2*)(hd + jj + 2) = __floats2half2_rn(hv.z, hv.w);
        *(float4*)(cd + jj) = cv;
    }
}

// ---------------- GEMM machinery ----------------
#define STRDH 40                 // halves per smem row (32 + 8 pad)
#define STGA_H (64*STRDH)        // A region: 2560 halves
#define STGF_H (192*STRDH)       // stage: 7680 halves = 15360 B
#define NSTG_ 4

struct Seg { const __half* A; int lda; const __half* W; int ldw; int kt; };

__device__ __forceinline__ void gemm_ml(
    Seg s0, Seg s1, int cpk, int cbase,
    int rA, int cA, const int rW[2], const int cW[2], const int wrW[2],
    __half* smh, float acc[2][4][4], int wm, int wn, int g8, int tg)
{
    __syncthreads();   // protect smem reuse across phases

#pragma unroll
    for (int mi = 0; mi < 2; mi++)
#pragma unroll
        for (int ni = 0; ni < 4; ni++)
#pragma unroll
            for (int e = 0; e < 4; e++) acc[mi][ni][e] = 0.f;

    auto issue = [&](int c, int buf) {
        const __half* Ab; const __half* Wb; int la, lw, ko;
        if (c < s0.kt) { Ab = s0.A; Wb = s0.W; la = s0.lda; lw = s0.ldw; ko = c * 32; }
        else           { Ab = s1.A; Wb = s1.W; la = s1.lda; lw = s1.ldw; ko = (c - s0.kt) * 32; }
        __half* st = smh + buf * STGF_H;
        cp16(st + rA * STRDH + cA, Ab + (size_t)rA * la + ko + cA);
#pragma unroll
        for (int j = 0; j < 2; j++)
            cp16(st + STGA_H + rW[j] * STRDH + cW[j], Wb + (size_t)wrW[j] * lw + ko + cW[j]);
        asm volatile("cp.async.commit_group;\n");
    };

    const int npro = cpk < 3 ? cpk : 3;
    for (int s = 0; s < npro; s++) issue(cbase + s, s);

    for (int i = 0; i < cpk; i++) {
        const int rem = cpk - 1 - i;
        if (rem >= 2)      asm volatile("cp.async.wait_group 2;\n");
        else if (rem == 1) asm volatile("cp.async.wait_group 1;\n");
        else               asm volatile("cp.async.wait_group 0;\n");
        __syncthreads();
        if (i + 3 < cpk) issue(cbase + i + 3, (i + 3) & 3);

        const __half* stg = smh + (i & 3) * STGF_H;
        const uint32_t* pA = (const uint32_t*)stg + (wm * 32 + g8) * 20 + tg;
        const uint32_t* pB = (const uint32_t*)(stg + STGA_H) + (wn * 32 + g8) * 20 + tg;
#pragma unroll
        for (int kk = 0; kk < 2; kk++) {
            const int ko = kk * 8;
            uint32_t a0[4], a1[4], b[4][2];
            a0[0] = pA[ko];               a0[1] = pA[8 * 20 + ko];
            a0[2] = pA[ko + 4];           a0[3] = pA[8 * 20 + ko + 4];
            a1[0] = pA[16 * 20 + ko];     a1[1] = pA[24 * 20 + ko];
            a1[2] = pA[16 * 20 + ko + 4]; a1[3] = pA[24 * 20 + ko + 4];
#pragma unroll
            for (int ni = 0; ni < 4; ni++) {
                b[ni][0] = pB[ni * 8 * 20 + ko];
                b[ni][1] = pB[ni * 8 * 20 + ko + 4];
            }
#pragma unroll
            for (int ni = 0; ni < 4; ni++) {
                mma16(acc[0][ni], a0, b[ni]);
                mma16(acc[1][ni], a1, b[ni]);
            }
        }
    }
}

__device__ __forceinline__ void store_partial(float acc[2][4][4], int wm, int wn, int g8, int tg) {
    float* pp = g_part + (size_t)blockIdx.x * 8192;
#pragma unroll
    for (int mi = 0; mi < 2; mi++)
#pragma unroll
        for (int ni = 0; ni < 4; ni++) {
            int r = wm * 32 + mi * 16 + g8, c = wn * 32 + ni * 8 + tg * 2;
            *(float2*)(pp + r * 128 + c)       = make_float2(acc[mi][ni][0], acc[mi][ni][1]);
            *(float2*)(pp + (r + 8) * 128 + c) = make_float2(acc[mi][ni][2], acc[mi][ni][3]);
        }
}

// reduce this CTA's row slice of its group's partials (L1-bypassing loads)
__device__ __forceinline__ void reduce_slice(float* red, int baseCta, int split, int sk, int rpc) {
    const float* pb = g_part + (size_t)baseCta * 8192 + sk * rpc * 128;
    for (int e4 = threadIdx.x; e4 < rpc * 32; e4 += NTHR) {
        float4 s = __ldcv((const float4*)(pb + e4 * 4));
        for (int p = 1; p < split; p++) {
            float4 v = __ldcv((const float4*)(pb + (size_t)p * 8192 + e4 * 4));
            s.x += v.x; s.y += v.y; s.z += v.z; s.w += v.w;
        }
        *(float4*)(red + e4 * 4) = s;
    }
    __syncthreads();
}

// ---------------- persistent megakernel ----------------
__global__ void __launch_bounds__(NTHR, 2) mega_kernel(
    const float* __restrict__ bi0, const float* __restrict__ bh0,
    const float* __restrict__ bi1, const float* __restrict__ bh1,
    float* __restrict__ outs, float* __restrict__ attns,
    float* __restrict__ hF, float* __restrict__ cF)
{
    extern __shared__ __align__(16) __half smh[];
    const int tid = threadIdx.x;
    const int w = tid >> 5, lane = tid & 31;
    const int wm = w >> 2, wn = w & 3;
    const int g8 = lane >> 2, tg = lane & 3;
    const int cta = blockIdx.x;

    const int rA = tid >> 2, cA = (tid & 3) * 8;
    int rW[2], cW[2];
#pragma unroll
    for (int j = 0; j < 2; j++) {
        int qk = j * 256 + tid;
        rW[j] = qk >> 2; cW[j] = (qk & 3) * 8;
    }

    float acc[2][4][4];

    // ---- startup A: precompute g_pre = inp @ Wih0_left^T (all t) ----
    for (int tile = cta; tile < 64 * 32; tile += NCTA) {
        const int t = tile >> 5, grp = tile & 31;
        const int n0 = grp * 32;
        int wrW[2];
#pragma unroll
        for (int j = 0; j < 2; j++) wrW[j] = (rW[j] >> 5) * H_ + n0 + (rW[j] & 31);
        Seg s{g_inph + (size_t)t * B_ * E_, E_, g_wih0h, EH_, 16};
        gemm_ml(s, s, 16, 0, rA, cA, rW, cW, wrW, smh, acc, wm, wn, g8, tg);
        float* dst = g_pre + (size_t)t * B_ * 4 * H_;
#pragma unroll
        for (int mi = 0; mi < 2; mi++)
#pragma unroll
            for (int ni = 0; ni < 4; ni++) {
                int r = wm * 32 + mi * 16 + g8, cc = wn * 32 + ni * 8 + tg * 2;
                int n = (cc >> 5) * H_ + n0 + (cc & 31);
                *(float2*)(dst + (size_t)r * 4096 + n)       = make_float2(acc[mi][ni][0], acc[mi][ni][1]);
                *(float2*)(dst + (size_t)(r + 8) * 4096 + n) = make_float2(acc[mi][ni][2], acc[mi][ni][3]);
            }
    }

    // ---- startup B: precompute ctxW = half(ctx @ WoutL^T) ----
    for (int tile = cta; tile < 128 * 8; tile += NCTA) {
        const int rt = tile >> 3, grp = tile & 7;
        const int nb = grp * 128;
        const int flatbase = rt * 64;
        int wrW[2];
#pragma unroll
        for (int j = 0; j < 2; j++) wrW[j] = nb + rW[j];
        Seg s{g_ctxh + (size_t)flatbase * H_, H_, g_wouth, 2 * H_, 32};
        gemm_ml(s, s, 32, 0, rA, cA, rW, cW, wrW, smh, acc, wm, wn, g8, tg);
#pragma unroll
        for (int mi = 0; mi < 2; mi++)
#pragma unroll
            for (int ni = 0; ni < 4; ni++) {
                int r = wm * 32 + mi * 16 + g8, cc = wn * 32 + ni * 8 + tg * 2;
                *(__half2*)(g_ctxwh + (size_t)(flatbase + r) * H_ + nb + cc) =
                    __floats2half2_rn(acc[mi][ni][0], acc[mi][ni][1]);
                *(__half2*)(g_ctxwh + (size_t)(flatbase + r + 8) * H_ + nb + cc) =
                    __floats2half2_rn(acc[mi][ni][2], acc[mi][ni][3]);
            }
    }
    arrive(&c_p4);   // startup counts as step -1 completion

    const int grpL = cta >> 3, skL = cta & 7;     // lstm: 32 grp x 8

    for (int t = 0; t < T_; t++) {
        const __half* fd  = t ? g_feedh : g_zerosh;
        const __half* h0p = g_hb0h + (size_t)(t & 1) * BH_;
        const __half* h1p = g_hb1h + (size_t)(t & 1) * BH_;
        __half* h0n = g_hb0h + (size_t)((t + 1) & 1) * BH_;
        __half* h1n = g_hb1h + (size_t)((t + 1) & 1) * BH_;
        float* red = (float*)smh;

        // ---- P0: lstm0 ----
        wait_ge(&c_p4, (unsigned long long)(t + 1) * 256);
        {
            const int n0 = grpL * 32;
            int wrW[2];
#pragma unroll
            for (int j = 0; j < 2; j++) wrW[j] = (rW[j] >> 5) * H_ + n0 + (rW[j] & 31);
            Seg s0{fd, H_, g_wih0h + E_, EH_, 32};
            Seg s1{h0p, H_, g_whh0h, H_, 32};
            gemm_ml(s0, s1, 8, skL * 8, rA, cA, rW, cW, wrW, smh, acc, wm, wn, g8, tg);
            store_partial(acc, wm, wn, g8, tg);
            arrive(&c_l0[grpL]);
            wait_ge(&c_l0[grpL], (unsigned long long)(t + 1) * 8);
            reduce_slice(red, grpL * 8, 8, skL, 8);
            const float* pre = g_pre + (size_t)t * B_ * 4 * H_;
            for (int e = tid; e < 8 * 32; e += NTHR) {
                int lm = e >> 5, j = e & 31;
                int m = skL * 8 + lm, n = n0 + j;
                float iv = red[lm * 128 + j]      + bi0[n]          + bh0[n]          + pre[(size_t)m * 4096 + n];
                float fv = red[lm * 128 + 32 + j] + bi0[H_ + n]     + bh0[H_ + n]     + pre[(size_t)m * 4096 + H_ + n];
                float gv = red[lm * 128 + 64 + j] + bi0[2 * H_ + n] + bh0[2 * H_ + n] + pre[(size_t)m * 4096 + 2 * H_ + n];
                float ov = red[lm * 128 + 96 + j] + bi0[3 * H_ + n] + bh0[3 * H_ + n] + pre[(size_t)m * 4096 + 3 * H_ + n];
                float cp = g_cb0[(size_t)m * H_ + n];
                float c2 = sigf(fv) * cp + sigf(iv) * tanhf(gv);
                float h2 = sigf(ov) * tanhf(c2);
                g_cb0[(size_t)m * H_ + n]  = c2;
                g_hraw0[(size_t)m * H_ + n] = h2;
                h0n[(size_t)m * H_ + n] = __float2half_rn(h2);
            }
            arrive(&c_p0);
        }

        // ---- P1: lstm1 ----
        wait_ge(&c_p0, (unsigned long long)(t + 1) * 256);
        {
            const int n0 = grpL * 32;
            int wrW[2];
#pragma unroll
            for (int j = 0; j < 2; j++) wrW[j] = (rW[j] >> 5) * H_ + n0 + (rW[j] & 31);
            Seg s0{h0n, H_, g_wih1h, H_, 32};
            Seg s1{h1p, H_, g_whh1h, H_, 32};
            gemm_ml(s0, s1, 8, skL * 8, rA, cA, rW, cW, wrW, smh, acc, wm, wn, g8, tg);
            store_partial(acc, wm, wn, g8, tg);
            arrive(&c_l1[grpL]);
            wait_ge(&c_l1[grpL], (unsigned long long)(t + 1) * 8);
            reduce_slice(red, grpL * 8, 8, skL, 8);
            for (int e = tid; e < 8 * 32; e += NTHR) {
                int lm = e >> 5, j = e & 31;
                int m = skL * 8 + lm, n = n0 + j;
                float iv = red[lm * 128 + j]      + bi1[n]          + bh1[n];
                float fv = red[lm * 128 + 32 + j] + bi1[H_ + n]     + bh1[H_ + n];
                float gv = red[lm * 128 + 64 + j] + bi1[2 * H_ + n] + bh1[2 * H_ + n];
                float ov = red[lm * 128 + 96 + j] + bi1[3 * H_ + n] + bh1[3 * H_ + n];
                float cp = g_cb1[(size_t)m * H_ + n];
                float c2 = sigf(fv) * cp + sigf(iv) * tanhf(gv);
                float h2 = sigf(ov) * tanhf(c2);
                g_cb1[(size_t)m * H_ + n]  = c2;
                g_hraw1[(size_t)m * H_ + n] = h2;
                h1n[(size_t)m * H_ + n] = __float2half_rn(h2);
            }
            arrive(&c_p1);
        }

        // ---- P2: q (ctas 0..127) || oh1 (ctas 128..255) ----
        wait_ge(&c_p1, (unsigned long long)(t + 1) * 256);
        {
            const int sub  = (cta < 128) ? cta : cta - 128;
            const int grpP = sub >> 4, skP = sub & 15;
            const int nb   = grpP * 128;
            const __half* W; int ldw; int baseCta;
            unsigned long long* gcnt; float* outp;
            if (cta < 128) { W = g_wah;        ldw = H_;     baseCta = grpP * 16;       gcnt = &c_q[grpP];  outp = g_q; }
            else           { W = g_wouth + H_; ldw = 2 * H_; baseCta = 128 + grpP * 16; gcnt = &c_oh[grpP]; outp = g_oh1; }
            int wrW[2];
#pragma unroll
            for (int j = 0; j < 2; j++) wrW[j] = nb + rW[j];
            Seg s0{h1n, H_, W, ldw, 32};
            gemm_ml(s0, s0, 2, skP * 2, rA, cA, rW, cW, wrW, smh, acc, wm, wn, g8, tg);
            store_partial(acc, wm, wn, g8, tg);
            arrive(gcnt);
            wait_ge(gcnt, (unsigned long long)(t + 1) * 16);
            reduce_slice(red, baseCta, 16, skP, 4);
            for (int e = tid; e < 4 * 128; e += NTHR) {
                int lm = e >> 7, c = e & 127;
                int m = skP * 4 + lm;
                outp[(size_t)m * H_ + nb + c] = red[e];
            }
            arrive((cta < 128) ? &c_p2q : &c_p2o);
        }

        // ---- P3: attention (all 256 CTAs; b = cta>>2, part = cta&3) ----
        wait_ge(&c_p2q, (unsigned long long)(t + 1) * 128);
        {
            const int b = cta >> 2, part = cta & 3;
            float* qs   = (float*)smh;
            float* sc   = qs + H_;
            float* sal  = sc + S_;
            float* red8 = sal + S_;
            __syncthreads();   // smem reuse
            ((float4*)qs)[tid] = __ldcv(((const float4*)(g_q + (size_t)b * H_)) + tid);
            __syncthreads();
            // scores: part covers 32 s (8 warps x 4)
#pragma unroll
            for (int i = 0; i < 4; i++) {
                const int s = part * 32 + w * 4 + i;
                const uint4* row = (const uint4*)(g_ctxh + ((size_t)s * B_ + b) * H_);
                float a2 = 0.f;
#pragma unroll
                for (int j = 0; j < 4; j++) {
                    uint4 cv = row[j * 32 + lane];
                    const float* qp = qs + j * 256 + lane * 8;
                    float2 c0 = __half22float2(*(const __half2*)&cv.x);
                    float2 c1 = __half22float2(*(const __half2*)&cv.y);
                    float2 c2 = __half22float2(*(const __half2*)&cv.z);
                    float2 c3 = __half22float2(*(const __half2*)&cv.w);
                    a2 += qp[0] * c0.x + qp[1] * c0.y + qp[2] * c1.x + qp[3] * c1.y
                        + qp[4] * c2.x + qp[5] * c2.y + qp[6] * c3.x + qp[7] * c3.y;
                }
#pragma unroll
                for (int o = 16; o > 0; o >>= 1) a2 += __shfl_xor_sync(0xFFFFFFFFu, a2, o);
                if (!lane) g_scores[b * S_ + s] = a2;
            }
            arrive(&c_at[b]);
            wait_ge(&c_at[b], (unsigned long long)(t + 1) * 4);
            if (tid < 128) sc[tid] = __ldcv(g_scores + b * S_ + tid);
            __syncthreads();
            float mx = -3.4e38f;
            if (tid < 128) mx = sc[tid];
#pragma unroll
            for (int o = 16; o > 0; o >>= 1) mx = fmaxf(mx, __shfl_xor_sync(0xFFFFFFFFu, mx, o));
            if (tid < 128 && !lane) red8[w] = mx;
            __syncthreads();
            const float gmx = fmaxf(fmaxf(red8[0], red8[1]), fmaxf(red8[2], red8[3]));
            float e = 0.f;
            if (tid < 128) { e = expf(sc[tid] - gmx); sal[tid] = e; }
            float se = e;
#pragma unroll
            for (int o = 16; o > 0; o >>= 1) se += __shfl_xor_sync(0xFFFFFFFFu, se, o);
            if (tid < 128 && !lane) red8[4 + w] = se;
            __syncthreads();
            const float inv = 1.f / (red8[4] + red8[5] + red8[6] + red8[7]);
            if (tid < 128) {
                float a = sal[tid] * inv;
                sal[tid] = a;
                if (part == 0) attns[(size_t)t * B_ * S_ + b * S_ + tid] = a;
            }
            __syncthreads();
            // fused output: outs[t,b,d] = tanh( sum_s sal[s]*ctxW[s,b,d] + oh1[b,d] )
            wait_ge(&c_p2o, (unsigned long long)(t + 1) * 128);
            const int d = part * 256 + tid;
            float a2 = 0.f;
#pragma unroll 8
            for (int s = 0; s < S_; s++)
                a2 += sal[s] * __half2float(g_ctxwh[((size_t)s * B_ + b) * H_ + d]);
            float v = tanhf(a2 + __ldcv(g_oh1 + (size_t)b * H_ + d));
            outs[(size_t)t * B_ * H_ + (size_t)b * H_ + d] = v;
            g_feedh[(size_t)b * H_ + d] = __float2half_rn(v);
            arrive(&c_p4);
        }
    }

    // ---- finalize ----
    wait_ge(&c_p4, (unsigned long long)(T_ + 1) * 256);
    {
        const int i = cta * NTHR + tid;   // exactly BH_
        hF[i]       = __ldcv(g_hraw0 + i);
        hF[BH_ + i] = __ldcv(g_hraw1 + i);
        cF[i]       = __ldcv(g_cb0 + i);
        cF[BH_ + i] = __ldcv(g_cb1 + i);
    }
}

// ---------------- host launcher ----------------
extern "C" void kernel_launch(void* const* d_in, const int* in_sizes, int n_in,
                              void* d_out, int out_size) {
    const float* inp   = (const float*)d_in[0];
    const float* ctx   = (const float*)d_in[1];
    const float* h0in  = (const float*)d_in[2];
    const float* c0in  = (const float*)d_in[3];
    const float* W_ih0 = (const float*)d_in[4];
    const float* b_ih0 = (const float*)d_in[5];
    const float* W_hh0 = (const float*)d_in[6];
    const float* b_hh0 = (const float*)d_in[7];
    const float* W_ih1 = (const float*)d_in[8];
    const float* b_ih1 = (const float*)d_in[9];
    const float* W_hh1 = (const float*)d_in[10];
    const float* b_hh1 = (const float*)d_in[11];
    const float* W_a   = (const float*)d_in[12];
    const float* W_out = (const float*)d_in[13];

    float* out   = (float*)d_out;
    float* outs  = out;                 // (T,B,H)
    float* hF    = out + TBH_;          // (2,B,H)
    float* cF    = hF + 2 * BH_;        // (2,B,H)
    float* attns = cF + 2 * BH_;        // (T,B,S)

    const int smemB = NSTG_ * STGF_H * sizeof(__half);   // 61440
    static int attrSet = 0;
    if (!attrSet) {
        cudaFuncSetAttribute(mega_kernel, cudaFuncAttributeMaxDynamicSharedMemorySize, smemB);
        attrSet = 1;
    }

    prep_weights<<<2048, 512>>>(W_ih0, W_hh0, W_ih1, W_hh1, W_a, W_out);
    prep_state<<<2048, 512>>>(inp, ctx, h0in, c0in);
    mega_kernel<<<NCTA, NTHR, smemB>>>(b_ih0, b_hh0, b_ih1, b_hh1, outs, attns, hF, cF);
}

// round 15
// speedup vs baseline: 1.3342x; 1.3342x over previous
#include <cuda_runtime.h>
#include <cuda_fp16.h>
#include <math.h>
#include <stdint.h>

#define T_  64
#define B_  64
#define S_  128
#define E_  512
#define H_  1024
#define EH_ 1536
#define BH_ (B_*H_)
#define TBH_ ((size_t)T_*B_*H_)
#define NCTA 256
#define NTHR 256

// ---------------- scratch (device globals; zero-init) ----------------
__device__ __align__(16) __half g_wih0h[(size_t)4*H_*EH_];
__device__ __align__(16) __half g_whh0h[(size_t)4*H_*H_];
__device__ __align__(16) __half g_wih1h[(size_t)4*H_*H_];
__device__ __align__(16) __half g_whh1h[(size_t)4*H_*H_];
__device__ __align__(16) __half g_wah[(size_t)H_*H_];
__device__ __align__(16) __half g_wouth[(size_t)H_*2*H_];
__device__ __align__(16) __half g_inph[(size_t)T_*B_*E_];
__device__ __align__(16) __half g_ctxh[(size_t)S_*B_*H_];
__device__ __align__(16) __half g_hb0h[2*BH_];
__device__ __align__(16) __half g_hb1h[2*BH_];
__device__ __align__(16) __half g_cvech[BH_];
__device__ __align__(16) __half g_feedh[BH_];
__device__ __align__(16) __half g_zerosh[BH_];   // never written -> 0
__device__ __align__(16) float g_hraw0[BH_];
__device__ __align__(16) float g_hraw1[BH_];
__device__ __align__(16) float g_cb0[BH_];
__device__ __align__(16) float g_cb1[BH_];
__device__ __align__(16) float g_q[BH_];
__device__ __align__(16) float g_oh1[BH_];
__device__ __align__(16) float g_scores[B_*S_];
__device__ __align__(16) float g_pre[(size_t)T_*B_*4*H_];   // inp proj (fp32)
__device__ __align__(16) float g_part[(size_t)NCTA*8192];   // split-K partials

// epoch counters (zeroed by prep_state every call)
__device__ unsigned long long c_l0[32], c_l1[32], c_q[8], c_oh[8], c_cv[8], c_at[64];
__device__ unsigned long long c_p0, c_p1, c_p2, c_p3, c_p3o, c_p4;

__device__ __forceinline__ float sigf(float x) { return 1.f / (1.f + expf(-x)); }

__device__ __forceinline__ void cp16(void* dst, const void* src) {
    unsigned s = (unsigned)__cvta_generic_to_shared(dst);
    asm volatile("cp.async.cg.shared.global [%0], [%1], 16;\n" :: "r"(s), "l"(src));
}

__device__ __forceinline__ void mma16(float* c, const uint32_t* a, const uint32_t* b) {
    asm volatile(
        "mma.sync.aligned.m16n8k16.row.col.f32.f16.f16.f32 "
        "{%0,%1,%2,%3}, {%4,%5,%6,%7}, {%8,%9}, {%0,%1,%2,%3};\n"
        : "+f"(c[0]), "+f"(c[1]), "+f"(c[2]), "+f"(c[3])
        : "r"(a[0]), "r"(a[1]), "r"(a[2]), "r"(a[3]), "r"(b[0]), "r"(b[1]));
}

__device__ __forceinline__ void arrive(unsigned long long* c) {
    __threadfence();
    __syncthreads();
    if (threadIdx.x == 0) atomicAdd(c, 1ULL);
}
__device__ __forceinline__ void wait_ge(unsigned long long* c, unsigned long long tgt) {
    if (threadIdx.x == 0) {
        unsigned long long v;
        do {
            asm volatile("ld.acquire.gpu.u64 %0, [%1];" : "=l"(v) : "l"(c));
        } while (v < tgt);
    }
    __syncthreads();
}

// ---------------- prep kernels (vectorized) ----------------
__global__ __launch_bounds__(512) void prep_weights(
    const float* __restrict__ wih0, const float* __restrict__ whh0,
    const float* __restrict__ wih1, const float* __restrict__ whh1,
    const float* __restrict__ wa,   const float* __restrict__ wout) {
    const size_t n0 = (size_t)4 * H_ * EH_;
    const size_t n1 = (size_t)4 * H_ * H_;
    const size_t n2 = (size_t)H_ * H_;
    const size_t n3 = (size_t)H_ * 2 * H_;
    const size_t tot4 = (n0 + 3 * n1 + n2 + n3) >> 2;
    for (size_t i4 = (size_t)blockIdx.x * blockDim.x + threadIdx.x; i4 < tot4;
         i4 += (size_t)gridDim.x * blockDim.x) {
        size_t j = i4 << 2; const float* s; __half* d;
        if (j < n0) { s = wih0 + j; d = g_wih0h + j; }
        else { j -= n0;
        if (j < n1) { s = whh0 + j; d = g_whh0h + j; }
        else { j -= n1;
        if (j < n1) { s = wih1 + j; d = g_wih1h + j; }
        else { j -= n1;
        if (j < n1) { s = whh1 + j; d = g_whh1h + j; }
        else { j -= n1;
        if (j < n2) { s = wa + j;   d = g_wah + j; }
        else { j -= n2; s = wout + j; d = g_wouth + j; } } } } }
        float4 v = *(const float4*)s;
        *(__half2*)(d)     = __floats2half2_rn(v.x, v.y);
        *(__half2*)(d + 2) = __floats2half2_rn(v.z, v.w);
    }
}

__global__ __launch_bounds__(512) void prep_state(const float* __restrict__ inp,
                                                  const float* __restrict__ ctx,
                                                  const float* __restrict__ h0,
                                                  const float* __restrict__ c0) {
    if (blockIdx.x == 0) {
        int t = threadIdx.x;
        if (t < 32) { c_l0[t] = 0; c_l1[t] = 0; }
        if (t < 8)  { c_q[t] = 0; c_oh[t] = 0; c_cv[t] = 0; }
        if (t < 64) c_at[t] = 0;
        if (t == 0) { c_p0 = 0; c_p1 = 0; c_p2 = 0; c_p3 = 0; c_p3o = 0; c_p4 = 0; }
    }
    const size_t ninp = (size_t)T_ * B_ * E_;
    const size_t nctx = (size_t)S_ * B_ * H_;
    const size_t tot4 = (ninp + nctx + 2 * BH_) >> 2;
    for (size_t i4 = (size_t)blockIdx.x * blockDim.x + threadIdx.x; i4 < tot4;
         i4 += (size_t)gridDim.x * blockDim.x) {
        size_t j = i4 << 2;
        if (j < ninp) {
            float4 v = *(const float4*)(inp + j);
            *(__half2*)(g_inph + j)     = __floats2half2_rn(v.x, v.y);
            *(__half2*)(g_inph + j + 2) = __floats2half2_rn(v.z, v.w);
            continue;
        }
        j -= ninp;
        if (j < nctx) {
            float4 v = *(const float4*)(ctx + j);
            *(__half2*)(g_ctxh + j)     = __floats2half2_rn(v.x, v.y);
            *(__half2*)(g_ctxh + j + 2) = __floats2half2_rn(v.z, v.w);
            continue;
        }
        j -= nctx;
        float4 hv = *(const float4*)(h0 + j);
        float4 cv = *(const float4*)(c0 + j);
        __half* hd; float* cd; size_t jj;
        if (j < BH_) { jj = j; hd = g_hb0h; cd = g_cb0; }
        else { jj = j - BH_; hd = g_hb1h; cd = g_cb1; }
        *(__half2*)(hd + jj)     = __floats2half2_rn(hv.x, hv.y);
        *(__half2*)(hd + jj + 2) = __floats2half2_rn(hv.z, hv.w);
        *(float4*)(cd + jj) = cv;
    }
}

// ---------------- GEMM machinery ----------------
#define STRDH 40                 // halves per smem row (32 + 8 pad)
#define STGA_H (64*STRDH)        // A region: 2560 halves
#define STGF_H (192*STRDH)       // stage: 7680 halves = 15360 B
#define NSTG_ 4

struct Seg { const __half* A; int lda; const __half* W; int ldw; int kt; };

__device__ __forceinline__ void gemm_ml(
    Seg s0, Seg s1, int cpk, int cbase,
    int rA, int cA, const int rW[2], const int cW[2], const int wrW[2],
    __half* smh, float acc[2][4][4], int wm, int wn, int g8, int tg)
{
    __syncthreads();   // protect smem reuse across phases

#pragma unroll
    for (int mi = 0; mi < 2; mi++)
#pragma unroll
        for (int ni = 0; ni < 4; ni++)
#pragma unroll
            for (int e = 0; e < 4; e++) acc[mi][ni][e] = 0.f;

    auto issue = [&](int c, int buf) {
        const __half* Ab; const __half* Wb; int la, lw, ko;
        if (c < s0.kt) { Ab = s0.A; Wb = s0.W; la = s0.lda; lw = s0.ldw; ko = c * 32; }
        else           { Ab = s1.A; Wb = s1.W; la = s1.lda; lw = s1.ldw; ko = (c - s0.kt) * 32; }
        __half* st = smh + buf * STGF_H;
        cp16(st + rA * STRDH + cA, Ab + (size_t)rA * la + ko + cA);
#pragma unroll
        for (int j = 0; j < 2; j++)
            cp16(st + STGA_H + rW[j] * STRDH + cW[j], Wb + (size_t)wrW[j] * lw + ko + cW[j]);
        asm volatile("cp.async.commit_group;\n");
    };

    const int npro = cpk < 3 ? cpk : 3;
    for (int s = 0; s < npro; s++) issue(cbase + s, s);

    for (int i = 0; i < cpk; i++) {
        const int rem = cpk - 1 - i;
        if (rem >= 2)      asm volatile("cp.async.wait_group 2;\n");
        else if (rem == 1) asm volatile("cp.async.wait_group 1;\n");
        else               asm volatile("cp.async.wait_group 0;\n");
        __syncthreads();
        if (i + 3 < cpk) issue(cbase + i + 3, (i + 3) & 3);

        const __half* stg = smh + (i & 3) * STGF_H;
        const uint32_t* pA = (const uint32_t*)stg + (wm * 32 + g8) * 20 + tg;
        const uint32_t* pB = (const uint32_t*)(stg + STGA_H) + (wn * 32 + g8) * 20 + tg;
#pragma unroll
        for (int kk = 0; kk < 2; kk++) {
            const int ko = kk * 8;
            uint32_t a0[4], a1[4], b[4][2];
            a0[0] = pA[ko];               a0[1] = pA[8 * 20 + ko];
            a0[2] = pA[ko + 4];           a0[3] = pA[8 * 20 + ko + 4];
            a1[0] = pA[16 * 20 + ko];     a1[1] = pA[24 * 20 + ko];
            a1[2] = pA[16 * 20 + ko + 4]; a1[3] = pA[24 * 20 + ko + 4];
#pragma unroll
            for (int ni = 0; ni < 4; ni++) {
                b[ni][0] = pB[ni * 8 * 20 + ko];
                b[ni][1] = pB[ni * 8 * 20 + ko + 4];
            }
#pragma unroll
            for (int ni = 0; ni < 4; ni++) {
                mma16(acc[0][ni], a0, b[ni]);
                mma16(acc[1][ni], a1, b[ni]);
            }
        }
    }
}

__device__ __forceinline__ void store_partial(float acc[2][4][4], int wm, int wn, int g8, int tg) {
    float* pp = g_part + (size_t)blockIdx.x * 8192;
#pragma unroll
    for (int mi = 0; mi < 2; mi++)
#pragma unroll
        for (int ni = 0; ni < 4; ni++) {
            int r = wm * 32 + mi * 16 + g8, c = wn * 32 + ni * 8 + tg * 2;
            *(float2*)(pp + r * 128 + c)       = make_float2(acc[mi][ni][0], acc[mi][ni][1]);
            *(float2*)(pp + (r + 8) * 128 + c) = make_float2(acc[mi][ni][2], acc[mi][ni][3]);
        }
}

// reduce this CTA's row slice of its group's partials (L1-bypassing loads)
__device__ __forceinline__ void reduce_slice(float* red, int baseCta, int split, int sk, int rpc) {
    const float* pb = g_part + (size_t)baseCta * 8192 + sk * rpc * 128;
    for (int e4 = threadIdx.x; e4 < rpc * 32; e4 += NTHR) {
        float4 s = __ldcv((const float4*)(pb + e4 * 4));
        for (int p = 1; p < split; p++) {
            float4 v = __ldcv((const float4*)(pb + (size_t)p * 8192 + e4 * 4));
            s.x += v.x; s.y += v.y; s.z += v.z; s.w += v.w;
        }
        *(float4*)(red + e4 * 4) = s;
    }
    __syncthreads();
}

// ---------------- persistent megakernel ----------------
__global__ void __launch_bounds__(NTHR, 2) mega_kernel(
    const float* __restrict__ bi0, const float* __restrict__ bh0,
    const float* __restrict__ bi1, const float* __restrict__ bh1,
    float* __restrict__ outs, float* __restrict__ attns,
    float* __restrict__ hF, float* __restrict__ cF)
{
    extern __shared__ __align__(16) __half smh[];
    const int tid = threadIdx.x;
    const int w = tid >> 5, lane = tid & 31;
    const int wm = w >> 2, wn = w & 3;
    const int g8 = lane >> 2, tg = lane & 3;
    const int cta = blockIdx.x;

    const int rA = tid >> 2, cA = (tid & 3) * 8;
    int rW[2], cW[2];
#pragma unroll
    for (int j = 0; j < 2; j++) {
        int qk = j * 256 + tid;
        rW[j] = qk >> 2; cW[j] = (qk & 3) * 8;
    }

    float acc[2][4][4];

    // ---- startup: precompute g_pre = inp @ Wih0_left^T (all t) ----
    for (int tile = cta; tile < 64 * 32; tile += NCTA) {
        const int t = tile >> 5, grp = tile & 31;
        const int n0 = grp * 32;
        int wrW[2];
#pragma unroll
        for (int j = 0; j < 2; j++) wrW[j] = (rW[j] >> 5) * H_ + n0 + (rW[j] & 31);
        Seg s{g_inph + (size_t)t * B_ * E_, E_, g_wih0h, EH_, 16};
        gemm_ml(s, s, 16, 0, rA, cA, rW, cW, wrW, smh, acc, wm, wn, g8, tg);
        float* dst = g_pre + (size_t)t * B_ * 4 * H_;
#pragma unroll
        for (int mi = 0; mi < 2; mi++)
#pragma unroll
            for (int ni = 0; ni < 4; ni++) {
                int r = wm * 32 + mi * 16 + g8, cc = wn * 32 + ni * 8 + tg * 2;
                int n = (cc >> 5) * H_ + n0 + (cc & 31);
                *(float2*)(dst + (size_t)r * 4096 + n)       = make_float2(acc[mi][ni][0], acc[mi][ni][1]);
                *(float2*)(dst + (size_t)(r + 8) * 4096 + n) = make_float2(acc[mi][ni][2], acc[mi][ni][3]);
            }
    }
    arrive(&c_p4);   // startup counts as step -1 completion

    const int grpL = cta >> 3, skL = cta & 7;     // lstm: 32 grp x 8

    for (int t = 0; t < T_; t++) {
        const __half* fd  = t ? g_feedh : g_zerosh;
        const __half* h0p = g_hb0h + (size_t)(t & 1) * BH_;
        const __half* h1p = g_hb1h + (size_t)(t & 1) * BH_;
        __half* h0n = g_hb0h + (size_t)((t + 1) & 1) * BH_;
        __half* h1n = g_hb1h + (size_t)((t + 1) & 1) * BH_;
        float* red = (float*)smh;

        // ---- P0: lstm0 ----
        wait_ge(&c_p4, (unsigned long long)(t + 1) * 256);
        {
            const int n0 = grpL * 32;
            int wrW[2];
#pragma unroll
            for (int j = 0; j < 2; j++) wrW[j] = (rW[j] >> 5) * H_ + n0 + (rW[j] & 31);
            Seg s0{fd, H_, g_wih0h + E_, EH_, 32};
            Seg s1{h0p, H_, g_whh0h, H_, 32};
            gemm_ml(s0, s1, 8, skL * 8, rA, cA, rW, cW, wrW, smh, acc, wm, wn, g8, tg);
            store_partial(acc, wm, wn, g8, tg);
            arrive(&c_l0[grpL]);
            wait_ge(&c_l0[grpL], (unsigned long long)(t + 1) * 8);
            reduce_slice(red, grpL * 8, 8, skL, 8);
            const float* pre = g_pre + (size_t)t * B_ * 4 * H_;
            for (int e = tid; e < 8 * 32; e += NTHR) {
                int lm = e >> 5, j = e & 31;
                int m = skL * 8 + lm, n = n0 + j;
                float iv = red[lm * 128 + j]      + bi0[n]          + bh0[n]          + pre[(size_t)m * 4096 + n];
                float fv = red[lm * 128 + 32 + j] + bi0[H_ + n]     + bh0[H_ + n]     + pre[(size_t)m * 4096 + H_ + n];
                float gv = red[lm * 128 + 64 + j] + bi0[2 * H_ + n] + bh0[2 * H_ + n] + pre[(size_t)m * 4096 + 2 * H_ + n];
                float ov = red[lm * 128 + 96 + j] + bi0[3 * H_ + n] + bh0[3 * H_ + n] + pre[(size_t)m * 4096 + 3 * H_ + n];
                float cp = g_cb0[(size_t)m * H_ + n];
                float c2 = sigf(fv) * cp + sigf(iv) * tanhf(gv);
                float h2 = sigf(ov) * tanhf(c2);
                g_cb0[(size_t)m * H_ + n]  = c2;
                g_hraw0[(size_t)m * H_ + n] = h2;
                h0n[(size_t)m * H_ + n] = __float2half_rn(h2);
            }
            arrive(&c_p0);
        }

        // ---- P1: lstm1 ----
        wait_ge(&c_p0, (unsigned long long)(t + 1) * 256);
        {
            const int n0 = grpL * 32;
            int wrW[2];
#pragma unroll
            for (int j = 0; j < 2; j++) wrW[j] = (rW[j] >> 5) * H_ + n0 + (rW[j] & 31);
            Seg s0{h0n, H_, g_wih1h, H_, 32};
            Seg s1{h1p, H_, g_whh1h, H_, 32};
            gemm_ml(s0, s1, 8, skL * 8, rA, cA, rW, cW, wrW, smh, acc, wm, wn, g8, tg);
            store_partial(acc, wm, wn, g8, tg);
            arrive(&c_l1[grpL]);
            wait_ge(&c_l1[grpL], (unsigned long long)(t + 1) * 8);
            reduce_slice(red, grpL * 8, 8, skL, 8);
            for (int e = tid; e < 8 * 32; e += NTHR) {
                int lm = e >> 5, j = e & 31;
                int m = skL * 8 + lm, n = n0 + j;
                float iv = red[lm * 128 + j]      + bi1[n]          + bh1[n];
                float fv = red[lm * 128 + 32 + j] + bi1[H_ + n]     + bh1[H_ + n];
                float gv = red[lm * 128 + 64 + j] + bi1[2 * H_ + n] + bh1[2 * H_ + n];
                float ov = red[lm * 128 + 96 + j] + bi1[3 * H_ + n] + bh1[3 * H_ + n];
                float cp = g_cb1[(size_t)m * H_ + n];
                float c2 = sigf(fv) * cp + sigf(iv) * tanhf(gv);
                float h2 = sigf(ov) * tanhf(c2);
                g_cb1[(size_t)m * H_ + n]  = c2;
                g_hraw1[(size_t)m * H_ + n] = h2;
                h1n[(size_t)m * H_ + n] = __float2half_rn(h2);
            }
            arrive(&c_p1);
        }

        // ---- P2: q = h1 @ Wa^T (all 256 CTAs, 8 grp x 32 split, cpk=1) ----
        wait_ge(&c_p1, (unsigned long long)(t + 1) * 256);
        {
            const int grpQ = cta >> 5, skQ = cta & 31;
            const int nb = grpQ * 128;
            int wrW[2];
#pragma unroll
            for (int j = 0; j < 2; j++) wrW[j] = nb + rW[j];
            Seg s0{h1n, H_, g_wah, H_, 32};
            gemm_ml(s0, s0, 1, skQ, rA, cA, rW, cW, wrW, smh, acc, wm, wn, g8, tg);
            store_partial(acc, wm, wn, g8, tg);
            arrive(&c_q[grpQ]);
            wait_ge(&c_q[grpQ], (unsigned long long)(t + 1) * 32);
            reduce_slice(red, grpQ * 32, 32, skQ, 2);
            for (int e = tid; e < 2 * 128; e += NTHR) {
                int lm = e >> 7, c = e & 127;
                int m = skQ * 2 + lm;
                g_q[(size_t)m * H_ + nb + c] = red[e];
            }
            arrive(&c_p2);
        }

        // ---- P3: attention (CTAs 0..127) || oh1 GEMM (CTAs 128..255) ----
        wait_ge(&c_p2, (unsigned long long)(t + 1) * 256);
        if (cta < 128) {
            const int b = cta >> 1, part = cta & 1;
            float* qs   = (float*)smh;
            float* sc   = qs + H_;
            float* sal  = sc + S_;
            float* red8 = sal + S_;
            __syncthreads();   // smem reuse
            ((float4*)qs)[tid] = __ldcv(((const float4*)(g_q + (size_t)b * H_)) + tid);
            __syncthreads();
            const int sbase = part * 64;
#pragma unroll
            for (int i = 0; i < 8; i++) {
                const int s = sbase + w * 8 + i;
                const uint4* row = (const uint4*)(g_ctxh + ((size_t)s * B_ + b) * H_);
                float a2 = 0.f;
#pragma unroll
                for (int j = 0; j < 4; j++) {
                    uint4 cv = row[j * 32 + lane];
                    const float* qp = qs + j * 256 + lane * 8;
                    float2 c0 = __half22float2(*(const __half2*)&cv.x);
                    float2 c1 = __half22float2(*(const __half2*)&cv.y);
                    float2 c2 = __half22float2(*(const __half2*)&cv.z);
                    float2 c3 = __half22float2(*(const __half2*)&cv.w);
                    a2 += qp[0] * c0.x + qp[1] * c0.y + qp[2] * c1.x + qp[3] * c1.y
                        + qp[4] * c2.x + qp[5] * c2.y + qp[6] * c3.x + qp[7] * c3.y;
                }
#pragma unroll
                for (int o = 16; o > 0; o >>= 1) a2 += __shfl_xor_sync(0xFFFFFFFFu, a2, o);
                if (!lane) g_scores[b * S_ + s] = a2;
            }
            arrive(&c_at[b]);
            wait_ge(&c_at[b], (unsigned long long)(t + 1) * 2);
            if (tid < 128) sc[tid] = __ldcv(g_scores + b * S_ + tid);
            __syncthreads();
            float mx = -3.4e38f;
            if (tid < 128) mx = sc[tid];
#pragma unroll
            for (int o = 16; o > 0; o >>= 1) mx = fmaxf(mx, __shfl_xor_sync(0xFFFFFFFFu, mx, o));
            if (tid < 128 && !lane) red8[w] = mx;
            __syncthreads();
            const float gmx = fmaxf(fmaxf(red8[0], red8[1]), fmaxf(red8[2], red8[3]));
            float e = 0.f;
            if (tid < 128) { e = expf(sc[tid] - gmx); sal[tid] = e; }
            float se = e;
#pragma unroll
            for (int o = 16; o > 0; o >>= 1) se += __shfl_xor_sync(0xFFFFFFFFu, se, o);
            if (tid < 128 && !lane) red8[4 + w] = se;
            __syncthreads();
            const float inv = 1.f / (red8[4] + red8[5] + red8[6] + red8[7]);
            if (tid < 128) {
                float a = sal[tid] * inv;
                sal[tid] = a;
                if (part == 0) attns[(size_t)t * B_ * S_ + b * S_ + tid] = a;
            }
            __syncthreads();
            // cvec: this part covers 512 dims (2 per thread)
            const int d0 = part * 512 + tid * 2;
            float2 a2 = make_float2(0.f, 0.f);
#pragma unroll 8
            for (int s = 0; s < S_; s++) {
                const float a = sal[s];
                float2 c = __half22float2(*(const __half2*)(g_ctxh + ((size_t)s * B_ + b) * H_ + d0));
                a2.x += a * c.x;
                a2.y += a * c.y;
            }
            *(__half2*)(g_cvech + (size_t)b * H_ + d0) = __floats2half2_rn(a2.x, a2.y);
            arrive(&c_p3);
        } else {
            // oh1 = h1 @ WoutR^T (8 grp x 16 split, cpk=2)
            const int sub = cta - 128;
            const int grpO = sub >> 4, skO = sub & 15;
            const int nb = grpO * 128;
            int wrW[2];
#pragma unroll
            for (int j = 0; j < 2; j++) wrW[j] = nb + rW[j];
            Seg s0{h1n, H_, g_wouth + H_, 2 * H_, 32};
            gemm_ml(s0, s0, 2, skO * 2, rA, cA, rW, cW, wrW, smh, acc, wm, wn, g8, tg);
            store_partial(acc, wm, wn, g8, tg);
            arrive(&c_oh[grpO]);
            wait_ge(&c_oh[grpO], (unsigned long long)(t + 1) * 16);
            reduce_slice(red, 128 + grpO * 16, 16, skO, 4);
            for (int e = tid; e < 4 * 128; e += NTHR) {
                int lm = e >> 7, c = e & 127;
                int m = skO * 4 + lm;
                g_oh1[(size_t)m * H_ + nb + c] = red[e];
            }
            arrive(&c_p3o);
        }

        // ---- P4: cvproj = tanh(cvec @ WoutL^T + oh1) ----
        wait_ge(&c_p3,  (unsigned long long)(t + 1) * 128);
        wait_ge(&c_p3o, (unsigned long long)(t + 1) * 128);
        {
            const int grpC = cta >> 5, skC = cta & 31;
            const int nb = grpC * 128;
            int wrW[2];
#pragma unroll
            for (int j = 0; j < 2; j++) wrW[j] = nb + rW[j];
            Seg s0{g_cvech, H_, g_wouth, 2 * H_, 32};
            gemm_ml(s0, s0, 1, skC, rA, cA, rW, cW, wrW, smh, acc, wm, wn, g8, tg);
            store_partial(acc, wm, wn, g8, tg);
            arrive(&c_cv[grpC]);
            wait_ge(&c_cv[grpC], (unsigned long long)(t + 1) * 32);
            reduce_slice(red, grpC * 32, 32, skC, 2);
            for (int e = tid; e < 2 * 128; e += NTHR) {
                int lm = e >> 7, c = e & 127;
                int m = skC * 2 + lm;
                float v = tanhf(red[e] + __ldcv(g_oh1 + (size_t)m * H_ + nb + c));
                outs[(size_t)t * B_ * H_ + (size_t)m * H_ + nb + c] = v;
                g_feedh[(size_t)m * H_ + nb + c] = __float2half_rn(v);
            }
            arrive(&c_p4);
        }
    }

    // ---- finalize ----
    wait_ge(&c_p4, (unsigned long long)(T_ + 1) * 256);
    {
        const int i = cta * NTHR + tid;   // exactly BH_
        hF[i]       = __ldcv(g_hraw0 + i);
        hF[BH_ + i] = __ldcv(g_hraw1 + i);
        cF[i]       = __ldcv(g_cb0 + i);
        cF[BH_ + i] = __ldcv(g_cb1 + i);
    }
}

// ---------------- host launcher ----------------
extern "C" void kernel_launch(void* const* d_in, const int* in_sizes, int n_in,
                              void* d_out, int out_size) {
    const float* inp   = (const float*)d_in[0];
    const float* ctx   = (const float*)d_in[1];
    const float* h0in  = (const float*)d_in[2];
    const float* c0in  = (const float*)d_in[3];
    const float* W_ih0 = (const float*)d_in[4];
    const float* b_ih0 = (const float*)d_in[5];
    const float* W_hh0 = (const float*)d_in[6];
    const float* b_hh0 = (const float*)d_in[7];
    const float* W_ih1 = (const float*)d_in[8];
    const float* b_ih1 = (const float*)d_in[9];
    const float* W_hh1 = (const float*)d_in[10];
    const float* b_hh1 = (const float*)d_in[11];
    const float* W_a   = (const float*)d_in[12];
    const float* W_out = (const float*)d_in[13];

    float* out   = (float*)d_out;
    float* outs  = out;                 // (T,B,H)
    float* hF    = out + TBH_;          // (2,B,H)
    float* cF    = hF + 2 * BH_;        // (2,B,H)
    float* attns = cF + 2 * BH_;        // (T,B,S)

    const int smemB = NSTG_ * STGF_H * sizeof(__half);   // 61440
    static int attrSet = 0;
    if (!attrSet) {
        cudaFuncSetAttribute(mega_kernel, cudaFuncAttributeMaxDynamicSharedMemorySize, smemB);
        attrSet = 1;
    }

    prep_weights<<<2048, 512>>>(W_ih0, W_hh0, W_ih1, W_hh1, W_a, W_out);
    prep_state<<<2048, 512>>>(inp, ctx, h0in, c0in);
    mega_kernel<<<NCTA, NTHR, smemB>>>(b_ih0, b_hh0, b_ih1, b_hh1, outs, attns, hF, cF);
}

// round 16
// speedup vs baseline: 1.3772x; 1.0322x over previous
#include <cuda_runtime.h>
#include <cuda_fp16.h>
#include <math.h>
#include <stdint.h>

#define T_  64
#define B_  64
#define S_  128
#define E_  512
#define H_  1024
#define EH_ 1536
#define BH_ (B_*H_)
#define TBH_ ((size_t)T_*B_*H_)
#define NCTA 128
#define NTHR 512

// ---------------- scratch (device globals; zero-init) ----------------
__device__ __align__(16) __half g_wih0h[(size_t)4*H_*EH_];
__device__ __align__(16) __half g_whh0h[(size_t)4*H_*H_];
__device__ __align__(16) __half g_wih1h[(size_t)4*H_*H_];
__device__ __align__(16) __half g_whh1h[(size_t)4*H_*H_];
__device__ __align__(16) __half g_wah[(size_t)H_*H_];
__device__ __align__(16) __half g_wouth[(size_t)H_*2*H_];
__device__ __align__(16) __half g_inph[(size_t)T_*B_*E_];
__device__ __align__(16) __half g_ctxh[(size_t)S_*B_*H_];
__device__ __align__(16) __half g_hb0h[2*BH_];
__device__ __align__(16) __half g_hb1h[2*BH_];
__device__ __align__(16) __half g_cvech[BH_];
__device__ __align__(16) __half g_feedh[BH_];
__device__ __align__(16) __half g_zerosh[BH_];   // never written -> 0
__device__ __align__(16) float g_hraw0[BH_];
__device__ __align__(16) float g_hraw1[BH_];
__device__ __align__(16) float g_cb0[BH_];
__device__ __align__(16) float g_cb1[BH_];
__device__ __align__(16) float g_q[BH_];
__device__ __align__(16) float g_oh1[BH_];
__device__ __align__(16) float g_pre[(size_t)T_*B_*4*H_];    // inp proj (fp32)
__device__ __align__(16) float g_part[(size_t)NCTA*16384];   // split-K partials (64x256/CTA)

// epoch counters (zeroed by prep_state every call)
__device__ unsigned long long c_l0[16], c_l1[16], c_q[4], c_oh[4], c_cv[4];
__device__ unsigned long long c_p0, c_p1, c_p2, c_p3, c_p3o, c_p4;

__device__ __forceinline__ float sigf(float x) { return 1.f / (1.f + expf(-x)); }

__device__ __forceinline__ void cp16(void* dst, const void* src) {
    unsigned s = (unsigned)__cvta_generic_to_shared(dst);
    asm volatile("cp.async.cg.shared.global [%0], [%1], 16;\n" :: "r"(s), "l"(src));
}

__device__ __forceinline__ void mma16(float* c, const uint32_t* a, const uint32_t* b) {
    asm volatile(
        "mma.sync.aligned.m16n8k16.row.col.f32.f16.f16.f32 "
        "{%0,%1,%2,%3}, {%4,%5,%6,%7}, {%8,%9}, {%0,%1,%2,%3};\n"
        : "+f"(c[0]), "+f"(c[1]), "+f"(c[2]), "+f"(c[3])
        : "r"(a[0]), "r"(a[1]), "r"(a[2]), "r"(a[3]), "r"(b[0]), "r"(b[1]));
}

__device__ __forceinline__ void arrive(unsigned long long* c) {
    __threadfence();
    __syncthreads();
    if (threadIdx.x == 0) atomicAdd(c, 1ULL);
}
__device__ __forceinline__ void wait_ge(unsigned long long* c, unsigned long long tgt) {
    if (threadIdx.x == 0) {
        unsigned long long v;
        do {
            asm volatile("ld.acquire.gpu.u64 %0, [%1];" : "=l"(v) : "l"(c));
        } while (v < tgt);
    }
    __syncthreads();
}

// ---------------- prep kernels (vectorized) ----------------
__global__ __launch_bounds__(512) void prep_weights(
    const float* __restrict__ wih0, const float* __restrict__ whh0,
    const float* __restrict__ wih1, const float* __restrict__ whh1,
    const float* __restrict__ wa,   const float* __restrict__ wout) {
    const size_t n0 = (size_t)4 * H_ * EH_;
    const size_t n1 = (size_t)4 * H_ * H_;
    const size_t n2 = (size_t)H_ * H_;
    const size_t n3 = (size_t)H_ * 2 * H_;
    const size_t tot4 = (n0 + 3 * n1 + n2 + n3) >> 2;
    for (size_t i4 = (size_t)blockIdx.x * blockDim.x + threadIdx.x; i4 < tot4;
         i4 += (size_t)gridDim.x * blockDim.x) {
        size_t j = i4 << 2; const float* s; __half* d;
        if (j < n0) { s = wih0 + j; d = g_wih0h + j; }
        else { j -= n0;
        if (j < n1) { s = whh0 + j; d = g_whh0h + j; }
        else { j -= n1;
        if (j < n1) { s = wih1 + j; d = g_wih1h + j; }
        else { j -= n1;
        if (j < n1) { s = whh1 + j; d = g_whh1h + j; }
        else { j -= n1;
        if (j < n2) { s = wa + j;   d = g_wah + j; }
        else { j -= n2; s = wout + j; d = g_wouth + j; } } } } }
        float4 v = *(const float4*)s;
        *(__half2*)(d)     = __floats2half2_rn(v.x, v.y);
        *(__half2*)(d + 2) = __floats2half2_rn(v.z, v.w);
    }
}

__global__ __launch_bounds__(512) void prep_state(const float* __restrict__ inp,
                                                  const float* __restrict__ ctx,
                                                  const float* __restrict__ h0,
                                                  const float* __restrict__ c0) {
    if (blockIdx.x == 0) {
        int t = threadIdx.x;
        if (t < 16) { c_l0[t] = 0; c_l1[t] = 0; }
        if (t < 4)  { c_q[t] = 0; c_oh[t] = 0; c_cv[t] = 0; }
        if (t == 0) { c_p0 = 0; c_p1 = 0; c_p2 = 0; c_p3 = 0; c_p3o = 0; c_p4 = 0; }
    }
    const size_t ninp = (size_t)T_ * B_ * E_;
    const size_t nctx = (size_t)S_ * B_ * H_;
    const size_t tot4 = (ninp + nctx + 2 * BH_) >> 2;
    for (size_t i4 = (size_t)blockIdx.x * blockDim.x + threadIdx.x; i4 < tot4;
         i4 += (size_t)gridDim.x * blockDim.x) {
        size_t j = i4 << 2;
        if (j < ninp) {
            float4 v = *(const float4*)(inp + j);
            *(__half2*)(g_inph + j)     = __floats2half2_rn(v.x, v.y);
            *(__half2*)(g_inph + j + 2) = __floats2half2_rn(v.z, v.w);
            continue;
        }
        j -= ninp;
        if (j < nctx) {
            float4 v = *(const float4*)(ctx + j);
            *(__half2*)(g_ctxh + j)     = __floats2half2_rn(v.x, v.y);
            *(__half2*)(g_ctxh + j + 2) = __floats2half2_rn(v.z, v.w);
            continue;
        }
        j -= nctx;
        float4 hv = *(const float4*)(h0 + j);
        float4 cv = *(const float4*)(c0 + j);
        __half* hd; float* cd; size_t jj;
        if (j < BH_) { jj = j; hd = g_hb0h; cd = g_cb0; }
        else { jj = j - BH_; hd = g_hb1h; cd = g_cb1; }
        *(__half2*)(hd + jj)     = __floats2half2_rn(hv.x, hv.y);
        *(__half2*)(hd + jj + 2) = __floats2half2_rn(hv.z, hv.w);
        *(float4*)(cd + jj) = cv;
    }
}

// ---------------- GEMM machinery: CTA tile 64 x 256, 16 warps (2m x 8n) ----------------
#define STRDH 40                  // halves per smem row (32 + 8 pad)
#define STGA_H (64*STRDH)         // A region: 2560 halves
#define STGW_H (256*STRDH)        // W region: 10240 halves
#define STGF_H (STGA_H + STGW_H)  // stage: 12800 halves = 25600 B
#define NSTG_ 3

struct Seg { const __half* A; int lda; const __half* W; int ldw; int kt; };

__device__ __forceinline__ void gemm_ml(
    Seg s0, Seg s1, int cpk, int cbase, int gateMode, int n0,
    __half* smh, float acc[2][4][4], int wm, int wn, int g8, int tg)
{
    __syncthreads();   // protect smem reuse across phases

    const int tid = threadIdx.x;
    // copy maps: A 256 chunks (tid<256, 1 each), W 1024 chunks (2 each)
    const int rA = tid >> 2, cA = (tid & 3) * 8;
    int rWl[2], cWl[2], wrW[2];
#pragma unroll
    for (int j = 0; j < 2; j++) {
        int qk = j * 512 + tid;
        rWl[j] = qk >> 2; cWl[j] = (qk & 3) * 8;
        wrW[j] = gateMode ? ((rWl[j] >> 6) * H_ + n0 + (rWl[j] & 63)) : (n0 + rWl[j]);
    }

#pragma unroll
    for (int mi = 0; mi < 2; mi++)
#pragma unroll
        for (int ni = 0; ni < 4; ni++)
#pragma unroll
            for (int e = 0; e < 4; e++) acc[mi][ni][e] = 0.f;

    auto issue = [&](int c, int buf) {
        const __half* Ab; const __half* Wb; int la, lw, ko;
        if (c < s0.kt) { Ab = s0.A; Wb = s0.W; la = s0.lda; lw = s0.ldw; ko = c * 32; }
        else           { Ab = s1.A; Wb = s1.W; la = s1.lda; lw = s1.ldw; ko = (c - s0.kt) * 32; }
        __half* st = smh + buf * STGF_H;
        if (tid < 256)
            cp16(st + rA * STRDH + cA, Ab + (size_t)rA * la + ko + cA);
#pragma unroll
        for (int j = 0; j < 2; j++)
            cp16(st + STGA_H + rWl[j] * STRDH + cWl[j], Wb + (size_t)wrW[j] * lw + ko + cWl[j]);
        asm volatile("cp.async.commit_group;\n");
    };

    const int npro = cpk < 2 ? cpk : 2;
    for (int s = 0; s < npro; s++) issue(cbase + s, s);

    for (int i = 0; i < cpk; i++) {
        const int rem = cpk - 1 - i;
        if (rem >= 1) asm volatile("cp.async.wait_group 1;\n");
        else          asm volatile("cp.async.wait_group 0;\n");
        __syncthreads();
        if (i + 2 < cpk) issue(cbase + i + 2, (i + 2) % 3);

        const __half* stg = smh + (i % 3) * STGF_H;
        const uint32_t* pA = (const uint32_t*)stg + (wm * 32 + g8) * 20 + tg;
        const uint32_t* pB = (const uint32_t*)(stg + STGA_H) + (wn * 32 + g8) * 20 + tg;
#pragma unroll
        for (int kk = 0; kk < 2; kk++) {
            const int ko = kk * 8;
            uint32_t a0[4], a1[4], b[4][2];
            a0[0] = pA[ko];               a0[1] = pA[8 * 20 + ko];
            a0[2] = pA[ko + 4];           a0[3] = pA[8 * 20 + ko + 4];
            a1[0] = pA[16 * 20 + ko];     a1[1] = pA[24 * 20 + ko];
            a1[2] = pA[16 * 20 + ko + 4]; a1[3] = pA[24 * 20 + ko + 4];
#pragma unroll
            for (int ni = 0; ni < 4; ni++) {
                b[ni][0] = pB[ni * 8 * 20 + ko];
                b[ni][1] = pB[ni * 8 * 20 + ko + 4];
            }
#pragma unroll
            for (int ni = 0; ni < 4; ni++) {
                mma16(acc[0][ni], a0, b[ni]);
                mma16(acc[1][ni], a1, b[ni]);
            }
        }
    }
}

__device__ __forceinline__ void store_partial(float acc[2][4][4], int wm, int wn, int g8, int tg) {
    float* pp = g_part + (size_t)blockIdx.x * 16384;
#pragma unroll
    for (int mi = 0; mi < 2; mi++)
#pragma unroll
        for (int ni = 0; ni < 4; ni++) {
            int r = wm * 32 + mi * 16 + g8, c = wn * 32 + ni * 8 + tg * 2;
            *(float2*)(pp + r * 256 + c)       = make_float2(acc[mi][ni][0], acc[mi][ni][1]);
            *(float2*)(pp + (r + 8) * 256 + c) = make_float2(acc[mi][ni][2], acc[mi][ni][3]);
        }
}

// reduce this CTA's row slice of its group's partials (L1-bypassing loads)
__device__ __forceinline__ void reduce_slice(float* red, int baseCta, int split, int sk, int rpc) {
    const float* pb = g_part + (size_t)baseCta * 16384 + sk * rpc * 256;
    for (int e4 = threadIdx.x; e4 < rpc * 64; e4 += NTHR) {
        float4 s = __ldcv((const float4*)(pb + e4 * 4));
        for (int p = 1; p < split; p++) {
            float4 v = __ldcv((const float4*)(pb + (size_t)p * 16384 + e4 * 4));
            s.x += v.x; s.y += v.y; s.z += v.z; s.w += v.w;
        }
        *(float4*)(red + e4 * 4) = s;
    }
    __syncthreads();
}

// ---------------- persistent megakernel ----------------
__global__ void __launch_bounds__(NTHR, 1) mega_kernel(
    const float* __restrict__ bi0, const float* __restrict__ bh0,
    const float* __restrict__ bi1, const float* __restrict__ bh1,
    float* __restrict__ outs, float* __restrict__ attns,
    float* __restrict__ hF, float* __restrict__ cF)
{
    extern __shared__ __align__(16) __half smh[];
    const int tid = threadIdx.x;
    const int w = tid >> 5, lane = tid & 31;
    const int wm = w >> 3, wn = w & 7;
    const int g8 = lane >> 2, tg = lane & 3;
    const int cta = blockIdx.x;

    float acc[2][4][4];

    // ---- startup: precompute g_pre = inp @ Wih0_left^T (all t) ----
    for (int tile = cta; tile < 64 * 16; tile += NCTA) {
        const int t = tile >> 4, grp = tile & 15;
        const int n0 = grp * 64;
        Seg s{g_inph + (size_t)t * B_ * E_, E_, g_wih0h, EH_, 16};
        gemm_ml(s, s, 16, 0, 1, n0, smh, acc, wm, wn, g8, tg);
        float* dst = g_pre + (size_t)t * B_ * 4 * H_;
#pragma unroll
        for (int mi = 0; mi < 2; mi++)
#pragma unroll
            for (int ni = 0; ni < 4; ni++) {
                int r = wm * 32 + mi * 16 + g8, cc = wn * 32 + ni * 8 + tg * 2;
                int n = (cc >> 6) * H_ + n0 + (cc & 63);
                *(float2*)(dst + (size_t)r * 4096 + n)       = make_float2(acc[mi][ni][0], acc[mi][ni][1]);
                *(float2*)(dst + (size_t)(r + 8) * 4096 + n) = make_float2(acc[mi][ni][2], acc[mi][ni][3]);
            }
    }
    arrive(&c_p4);   // startup counts as step -1 completion

    const int grpL = cta >> 3, skL = cta & 7;     // lstm: 16 grp x 8 split

    for (int t = 0; t < T_; t++) {
        const __half* fd  = t ? g_feedh : g_zerosh;
        const __half* h0p = g_hb0h + (size_t)(t & 1) * BH_;
        const __half* h1p = g_hb1h + (size_t)(t & 1) * BH_;
        __half* h0n = g_hb0h + (size_t)((t + 1) & 1) * BH_;
        __half* h1n = g_hb1h + (size_t)((t + 1) & 1) * BH_;
        float* red = (float*)smh;

        // ---- P0: lstm0 ----
        wait_ge(&c_p4, (unsigned long long)(t + 1) * NCTA);
        {
            const int n0 = grpL * 64;
            Seg s0{fd, H_, g_wih0h + E_, EH_, 32};
            Seg s1{h0p, H_, g_whh0h, H_, 32};
            gemm_ml(s0, s1, 8, skL * 8, 1, n0, smh, acc, wm, wn, g8, tg);
            store_partial(acc, wm, wn, g8, tg);
            arrive(&c_l0[grpL]);
            wait_ge(&c_l0[grpL], (unsigned long long)(t + 1) * 8);
            reduce_slice(red, grpL * 8, 8, skL, 8);
            const float* pre = g_pre + (size_t)t * B_ * 4 * H_;
            for (int e = tid; e < 8 * 64; e += NTHR) {
                int lm = e >> 6, j = e & 63;
                int m = skL * 8 + lm, n = n0 + j;
                float iv = red[lm * 256 + j]       + bi0[n]          + bh0[n]          + pre[(size_t)m * 4096 + n];
                float fv = red[lm * 256 + 64 + j]  + bi0[H_ + n]     + bh0[H_ + n]     + pre[(size_t)m * 4096 + H_ + n];
                float gv = red[lm * 256 + 128 + j] + bi0[2 * H_ + n] + bh0[2 * H_ + n] + pre[(size_t)m * 4096 + 2 * H_ + n];
                float ov = red[lm * 256 + 192 + j] + bi0[3 * H_ + n] + bh0[3 * H_ + n] + pre[(size_t)m * 4096 + 3 * H_ + n];
                float cp = g_cb0[(size_t)m * H_ + n];
                float c2 = sigf(fv) * cp + sigf(iv) * tanhf(gv);
                float h2 = sigf(ov) * tanhf(c2);
                g_cb0[(size_t)m * H_ + n]   = c2;
                g_hraw0[(size_t)m * H_ + n] = h2;
                h0n[(size_t)m * H_ + n] = __float2half_rn(h2);
            }
            arrive(&c_p0);
        }

        // ---- P1: lstm1 ----
        wait_ge(&c_p0, (unsigned long long)(t + 1) * NCTA);
        {
            const int n0 = grpL * 64;
            Seg s0{h0n, H_, g_wih1h, H_, 32};
            Seg s1{h1p, H_, g_whh1h, H_, 32};
            gemm_ml(s0, s1, 8, skL * 8, 1, n0, smh, acc, wm, wn, g8, tg);
            store_partial(acc, wm, wn, g8, tg);
            arrive(&c_l1[grpL]);
            wait_ge(&c_l1[grpL], (unsigned long long)(t + 1) * 8);
            reduce_slice(red, grpL * 8, 8, skL, 8);
            for (int e = tid; e < 8 * 64; e += NTHR) {
                int lm = e >> 6, j = e & 63;
                int m = skL * 8 + lm, n = n0 + j;
                float iv = red[lm * 256 + j]       + bi1[n]          + bh1[n];
                float fv = red[lm * 256 + 64 + j]  + bi1[H_ + n]     + bh1[H_ + n];
                float gv = red[lm * 256 + 128 + j] + bi1[2 * H_ + n] + bh1[2 * H_ + n];
                float ov = red[lm * 256 + 192 + j] + bi1[3 * H_ + n] + bh1[3 * H_ + n];
                float cp = g_cb1[(size_t)m * H_ + n];
                float c2 = sigf(fv) * cp + sigf(iv) * tanhf(gv);
                float h2 = sigf(ov) * tanhf(c2);
                g_cb1[(size_t)m * H_ + n]   = c2;
                g_hraw1[(size_t)m * H_ + n] = h2;
                h1n[(size_t)m * H_ + n] = __float2half_rn(h2);
            }
            arrive(&c_p1);
        }

        // ---- P2: q = h1 @ Wa^T (4 grp x 32 split, cpk=1) ----
        wait_ge(&c_p1, (unsigned long long)(t + 1) * NCTA);
        {
            const int grpQ = cta >> 5, skQ = cta & 31;
            const int nb = grpQ * 256;
            Seg s0{h1n, H_, g_wah, H_, 32};
            gemm_ml(s0, s0, 1, skQ, 0, nb, smh, acc, wm, wn, g8, tg);
            store_partial(acc, wm, wn, g8, tg);
            arrive(&c_q[grpQ]);
            wait_ge(&c_q[grpQ], (unsigned long long)(t + 1) * 32);
            reduce_slice(red, grpQ * 32, 32, skQ, 2);
            for (int e = tid; e < 2 * 256; e += NTHR) {
                int lm = e >> 8, c = e & 255;
                int m = skQ * 2 + lm;
                g_q[(size_t)m * H_ + nb + c] = red[e];
            }
            arrive(&c_p2);
        }

        // ---- P3: attention (CTAs 0..63, fully CTA-local) || oh1 (CTAs 64..127) ----
        wait_ge(&c_p2, (unsigned long long)(t + 1) * NCTA);
        if (cta < 64) {
            const int b = cta;
            float* qs   = (float*)smh;
            float* sc   = qs + H_;
            float* sal  = sc + S_;
            float* red8 = sal + S_;
            __syncthreads();   // smem reuse
            ((float2*)qs)[tid] = __ldcv(((const float2*)(g_q + (size_t)b * H_)) + tid);
            __syncthreads();
            // scores: 16 warps x 8 s = 128
#pragma unroll
            for (int i = 0; i < 8; i++) {
                const int s = w * 8 + i;
                const uint4* row = (const uint4*)(g_ctxh + ((size_t)s * B_ + b) * H_);
                float a2 = 0.f;
#pragma unroll
                for (int j = 0; j < 4; j++) {
                    uint4 cv = row[j * 32 + lane];
                    const float* qp = qs + j * 256 + lane * 8;
                    float2 c0 = __half22float2(*(const __half2*)&cv.x);
                    float2 c1 = __half22float2(*(const __half2*)&cv.y);
                    float2 c2 = __half22float2(*(const __half2*)&cv.z);
                    float2 c3 = __half22float2(*(const __half2*)&cv.w);
                    a2 += qp[0] * c0.x + qp[1] * c0.y + qp[2] * c1.x + qp[3] * c1.y
                        + qp[4] * c2.x + qp[5] * c2.y + qp[6] * c3.x + qp[7] * c3.y;
                }
#pragma unroll
                for (int o = 16; o > 0; o >>= 1) a2 += __shfl_xor_sync(0xFFFFFFFFu, a2, o);
                if (!lane) sc[s] = a2;
            }
            __syncthreads();
            float mx = -3.4e38f;
            if (tid < 128) mx = sc[tid];
#pragma unroll
            for (int o = 16; o > 0; o >>= 1) mx = fmaxf(mx, __shfl_xor_sync(0xFFFFFFFFu, mx, o));
            if (tid < 128 && !lane) red8[w] = mx;
            __syncthreads();
            const float gmx = fmaxf(fmaxf(red8[0], red8[1]), fmaxf(red8[2], red8[3]));
            float e = 0.f;
            if (tid < 128) { e = expf(sc[tid] - gmx); sal[tid] = e; }
            float se = e;
#pragma unroll
            for (int o = 16; o > 0; o >>= 1) se += __shfl_xor_sync(0xFFFFFFFFu, se, o);
            if (tid < 128 && !lane) red8[4 + w] = se;
            __syncthreads();
            const float inv = 1.f / (red8[4] + red8[5] + red8[6] + red8[7]);
            if (tid < 128) {
                float a = sal[tid] * inv;
                sal[tid] = a;
                attns[(size_t)t * B_ * S_ + b * S_ + tid] = a;
            }
            __syncthreads();
            // cvec: 512 threads x 2 dims
            const int d0 = tid * 2;
            float2 a2 = make_float2(0.f, 0.f);
#pragma unroll 8
            for (int s = 0; s < S_; s++) {
                const float a = sal[s];
                float2 c = __half22float2(*(const __half2*)(g_ctxh + ((size_t)s * B_ + b) * H_ + d0));
                a2.x += a * c.x;
                a2.y += a * c.y;
            }
            *(__half2*)(g_cvech + (size_t)b * H_ + d0) = __floats2half2_rn(a2.x, a2.y);
            arrive(&c_p3);
        } else {
            // oh1 = h1 @ WoutR^T (4 grp x 16 split, cpk=2)
            const int sub = cta - 64;
            const int grpO = sub >> 4, skO = sub & 15;
            const int nb = grpO * 256;
            Seg s0{h1n, H_, g_wouth + H_, 2 * H_, 32};
            gemm_ml(s0, s0, 2, skO * 2, 0, nb, smh, acc, wm, wn, g8, tg);
            store_partial(acc, wm, wn, g8, tg);
            arrive(&c_oh[grpO]);
            wait_ge(&c_oh[grpO], (unsigned long long)(t + 1) * 16);
            reduce_slice(red, 64 + grpO * 16, 16, skO, 4);
            for (int e = tid; e < 4 * 256; e += NTHR) {
                int lm = e >> 8, c = e & 255;
                int m = skO * 4 + lm;
                g_oh1[(size_t)m * H_ + nb + c] = red[e];
            }
            arrive(&c_p3o);
        }

        // ---- P4: cvproj = tanh(cvec @ WoutL^T + oh1) (4 grp x 32 split, cpk=1) ----
        wait_ge(&c_p3,  (unsigned long long)(t + 1) * 64);
        wait_ge(&c_p3o, (unsigned long long)(t + 1) * 64);
        {
            const int grpC = cta >> 5, skC = cta & 31;
            const int nb = grpC * 256;
            Seg s0{g_cvech, H_, g_wouth, 2 * H_, 32};
            gemm_ml(s0, s0, 1, skC, 0, nb, smh, acc, wm, wn, g8, tg);
            store_partial(acc, wm, wn, g8, tg);
            arrive(&c_cv[grpC]);
            wait_ge(&c_cv[grpC], (unsigned long long)(t + 1) * 32);
            reduce_slice(red, grpC * 32, 32, skC, 2);
            for (int e = tid; e < 2 * 256; e += NTHR) {
                int lm = e >> 8, c = e & 255;
                int m = skC * 2 + lm;
                float v = tanhf(red[e] + __ldcv(g_oh1 + (size_t)m * H_ + nb + c));
                outs[(size_t)t * B_ * H_ + (size_t)m * H_ + nb + c] = v;
                g_feedh[(size_t)m * H_ + nb + c] = __float2half_rn(v);
            }
            arrive(&c_p4);
        }
    }

    // ---- finalize ----
    wait_ge(&c_p4, (unsigned long long)(T_ + 1) * NCTA);
    {
        const int i = cta * NTHR + tid;   // exactly BH_
        hF[i]       = __ldcv(g_hraw0 + i);
        hF[BH_ + i] = __ldcv(g_hraw1 + i);
        cF[i]       = __ldcv(g_cb0 + i);
        cF[BH_ + i] = __ldcv(g_cb1 + i);
    }
}

// ---------------- host launcher ----------------
extern "C" void kernel_launch(void* const* d_in, const int* in_sizes, int n_in,
                              void* d_out, int out_size) {
    const float* inp   = (const float*)d_in[0];
    const float* ctx   = (const float*)d_in[1];
    const float* h0in  = (const float*)d_in[2];
    const float* c0in  = (const float*)d_in[3];
    const float* W_ih0 = (const float*)d_in[4];
    const float* b_ih0 = (const float*)d_in[5];
    const float* W_hh0 = (const float*)d_in[6];
    const float* b_hh0 = (const float*)d_in[7];
    const float* W_ih1 = (const float*)d_in[8];
    const float* b_ih1 = (const float*)d_in[9];
    const float* W_hh1 = (const float*)d_in[10];
    const float* b_hh1 = (const float*)d_in[11];
    const float* W_a   = (const float*)d_in[12];
    const float* W_out = (const float*)d_in[13];

    float* out   = (float*)d_out;
    float* outs  = out;                 // (T,B,H)
    float* hF    = out + TBH_;          // (2,B,H)
    float* cF    = hF + 2 * BH_;        // (2,B,H)
    float* attns = cF + 2 * BH_;        // (T,B,S)

    const int smemB = NSTG_ * STGF_H * sizeof(__half);   // 76800
    static int attrSet = 0;
    if (!attrSet) {
        cudaFuncSetAttribute(mega_kernel, cudaFuncAttributeMaxDynamicSharedMemorySize, smemB);
        attrSet = 1;
    }

    prep_weights<<<2048, 512>>>(W_ih0, W_hh0, W_ih1, W_hh1, W_a, W_out);
    prep_state<<<2048, 512>>>(inp, ctx, h0in, c0in);
    mega_kernel<<<NCTA, NTHR, smemB>>>(b_ih0, b_hh0, b_ih1, b_hh1, outs, attns, hF, cF);
}

// round 17
// speedup vs baseline: 1.3822x; 1.0036x over previous
#include <cuda_runtime.h>
#include <cuda_fp16.h>
#include <math.h>
#include <stdint.h>

#define T_  64
#define B_  64
#define S_  128
#define E_  512
#define H_  1024
#define EH_ 1536
#define BH_ (B_*H_)
#define TBH_ ((size_t)T_*B_*H_)
#define NCTA 128
#define NTHR 512

// ---------------- scratch (device globals; zero-init) ----------------
__device__ __align__(16) __half g_wih0h[(size_t)4*H_*EH_];
__device__ __align__(16) __half g_whh0h[(size_t)4*H_*H_];
__device__ __align__(16) __half g_wih1h[(size_t)4*H_*H_];
__device__ __align__(16) __half g_whh1h[(size_t)4*H_*H_];
__device__ __align__(16) __half g_wat[(size_t)H_*H_];        // W_a transposed (half)
__device__ __align__(16) __half g_wouth[(size_t)H_*2*H_];
__device__ __align__(16) __half g_inph[(size_t)T_*B_*E_];
__device__ __align__(16) __half g_ctxh[(size_t)S_*B_*H_];
__device__ __align__(16) __half g_ctxph[(size_t)S_*B_*H_];   // ctx @ W_a (half, precomputed)
__device__ __align__(16) __half g_hb0h[2*BH_];
__device__ __align__(16) __half g_hb1h[2*BH_];
__device__ __align__(16) __half g_cvech[BH_];
__device__ __align__(16) __half g_feedh[BH_];
__device__ __align__(16) __half g_zerosh[BH_];   // never written -> 0
__device__ __align__(16) float g_hraw0[BH_];
__device__ __align__(16) float g_hraw1[BH_];
__device__ __align__(16) float g_cb0[BH_];
__device__ __align__(16) float g_cb1[BH_];
__device__ __align__(16) float g_oh1[BH_];
__device__ __align__(16) float g_pre[(size_t)T_*B_*4*H_];    // inp proj (fp32)
__device__ __align__(16) float g_part[(size_t)NCTA*16384];   // split-K partials (64x256/CTA)

// epoch counters (zeroed by prep_state every call)
__device__ unsigned long long c_l0[16], c_l1[16], c_oh[4], c_cv[4];
__device__ unsigned long long c_p0, c_p1, c_p3, c_p4;

__device__ __forceinline__ float sigf(float x) { return 1.f / (1.f + expf(-x)); }

__device__ __forceinline__ void cp16(void* dst, const void* src) {
    unsigned s = (unsigned)__cvta_generic_to_shared(dst);
    asm volatile("cp.async.cg.shared.global [%0], [%1], 16;\n" :: "r"(s), "l"(src));
}

__device__ __forceinline__ void mma16(float* c, const uint32_t* a, const uint32_t* b) {
    asm volatile(
        "mma.sync.aligned.m16n8k16.row.col.f32.f16.f16.f32 "
        "{%0,%1,%2,%3}, {%4,%5,%6,%7}, {%8,%9}, {%0,%1,%2,%3};\n"
        : "+f"(c[0]), "+f"(c[1]), "+f"(c[2]), "+f"(c[3])
        : "r"(a[0]), "r"(a[1]), "r"(a[2]), "r"(a[3]), "r"(b[0]), "r"(b[1]));
}

__device__ __forceinline__ void arrive(unsigned long long* c) {
    __threadfence();
    __syncthreads();
    if (threadIdx.x == 0) atomicAdd(c, 1ULL);
}
__device__ __forceinline__ void wait_ge(unsigned long long* c, unsigned long long tgt) {
    if (threadIdx.x == 0) {
        unsigned long long v;
        do {
            asm volatile("ld.acquire.gpu.u64 %0, [%1];" : "=l"(v) : "l"(c));
        } while (v < tgt);
    }
    __syncthreads();
}

// ---------------- prep kernels ----------------
__global__ __launch_bounds__(512) void prep_weights(
    const float* __restrict__ wih0, const float* __restrict__ whh0,
    const float* __restrict__ wih1, const float* __restrict__ whh1,
    const float* __restrict__ wout) {
    const size_t n0 = (size_t)4 * H_ * EH_;
    const size_t n1 = (size_t)4 * H_ * H_;
    const size_t n3 = (size_t)H_ * 2 * H_;
    const size_t tot4 = (n0 + 3 * n1 + n3) >> 2;
    for (size_t i4 = (size_t)blockIdx.x * blockDim.x + threadIdx.x; i4 < tot4;
         i4 += (size_t)gridDim.x * blockDim.x) {
        size_t j = i4 << 2; const float* s; __half* d;
        if (j < n0) { s = wih0 + j; d = g_wih0h + j; }
        else { j -= n0;
        if (j < n1) { s = whh0 + j; d = g_whh0h + j; }
        else { j -= n1;
        if (j < n1) { s = wih1 + j; d = g_wih1h + j; }
        else { j -= n1;
        if (j < n1) { s = whh1 + j; d = g_whh1h + j; }
        else { j -= n1; s = wout + j; d = g_wouth + j; } } } }
        float4 v = *(const float4*)s;
        *(__half2*)(d)     = __floats2half2_rn(v.x, v.y);
        *(__half2*)(d + 2) = __floats2half2_rn(v.z, v.w);
    }
}

// transpose W_a into half: wat[d, k] = wa[k, d]
__global__ __launch_bounds__(256) void prep_transpose(const float* __restrict__ wa) {
    __shared__ float tile[32][33];
    const int bx = blockIdx.x * 32, by = blockIdx.y * 32;
    const int tx = threadIdx.x & 31, ty = threadIdx.x >> 5;   // 32 x 8
#pragma unroll
    for (int r = 0; r < 32; r += 8)
        tile[ty + r][tx] = wa[(size_t)(by + ty + r) * H_ + bx + tx];
    __syncthreads();
#pragma unroll
    for (int r = 0; r < 32; r += 8)
        g_wat[(size_t)(bx + ty + r) * H_ + by + tx] = __float2half_rn(tile[tx][ty + r]);
}

__global__ __launch_bounds__(512) void prep_state(const float* __restrict__ inp,
                                                  const float* __restrict__ ctx,
                                                  const float* __restrict__ h0,
                                                  const float* __restrict__ c0) {
    if (blockIdx.x == 0) {
        int t = threadIdx.x;
        if (t < 16) { c_l0[t] = 0; c_l1[t] = 0; }
        if (t < 4)  { c_oh[t] = 0; c_cv[t] = 0; }
        if (t == 0) { c_p0 = 0; c_p1 = 0; c_p3 = 0; c_p4 = 0; }
    }
    const size_t ninp = (size_t)T_ * B_ * E_;
    const size_t nctx = (size_t)S_ * B_ * H_;
    const size_t tot4 = (ninp + nctx + 2 * BH_) >> 2;
    for (size_t i4 = (size_t)blockIdx.x * blockDim.x + threadIdx.x; i4 < tot4;
         i4 += (size_t)gridDim.x * blockDim.x) {
        size_t j = i4 << 2;
        if (j < ninp) {
            float4 v = *(const float4*)(inp + j);
            *(__half2*)(g_inph + j)     = __floats2half2_rn(v.x, v.y);
            *(__half2*)(g_inph + j + 2) = __floats2half2_rn(v.z, v.w);
            continue;
        }
        j -= ninp;
        if (j < nctx) {
            float4 v = *(const float4*)(ctx + j);
            *(__half2*)(g_ctxh + j)     = __floats2half2_rn(v.x, v.y);
            *(__half2*)(g_ctxh + j + 2) = __floats2half2_rn(v.z, v.w);
            continue;
        }
        j -= nctx;
        float4 hv = *(const float4*)(h0 + j);
        float4 cv = *(const float4*)(c0 + j);
        __half* hd; float* cd; size_t jj;
        if (j < BH_) { jj = j; hd = g_hb0h; cd = g_cb0; }
        else { jj = j - BH_; hd = g_hb1h; cd = g_cb1; }
        *(__half2*)(hd + jj)     = __floats2half2_rn(hv.x, hv.y);
        *(__half2*)(hd + jj + 2) = __floats2half2_rn(hv.z, hv.w);
        *(float4*)(cd + jj) = cv;
    }
}

// ---------------- GEMM machinery: CTA tile 64 x 256, 16 warps (2m x 8n) ----------------
#define STRDH 40                  // halves per smem row (32 + 8 pad)
#define STGA_H (64*STRDH)         // A region: 2560 halves
#define STGW_H (256*STRDH)        // W region: 10240 halves
#define STGF_H (STGA_H + STGW_H)  // stage: 12800 halves = 25600 B
#define NSTG_ 3

struct Seg { const __half* A; int lda; const __half* W; int ldw; int kt; };

__device__ __forceinline__ void gemm_ml(
    Seg s0, Seg s1, int cpk, int cbase, int gateMode, int n0,
    __half* smh, float acc[2][4][4], int wm, int wn, int g8, int tg)
{
    __syncthreads();   // protect smem reuse across phases

    const int tid = threadIdx.x;
    const int rA = tid >> 2, cA = (tid & 3) * 8;
    int rWl[2], cWl[2], wrW[2];
#pragma unroll
    for (int j = 0; j < 2; j++) {
        int qk = j * 512 + tid;
        rWl[j] = qk >> 2; cWl[j] = (qk & 3) * 8;
        wrW[j] = gateMode ? ((rWl[j] >> 6) * H_ + n0 + (rWl[j] & 63)) : (n0 + rWl[j]);
    }

#pragma unroll
    for (int mi = 0; mi < 2; mi++)
#pragma unroll
        for (int ni = 0; ni < 4; ni++)
#pragma unroll
            for (int e = 0; e < 4; e++) acc[mi][ni][e] = 0.f;

    auto issue = [&](int c, int buf) {
        const __half* Ab; const __half* Wb; int la, lw, ko;
        if (c < s0.kt) { Ab = s0.A; Wb = s0.W; la = s0.lda; lw = s0.ldw; ko = c * 32; }
        else           { Ab = s1.A; Wb = s1.W; la = s1.lda; lw = s1.ldw; ko = (c - s0.kt) * 32; }
        __half* st = smh + buf * STGF_H;
        if (tid < 256)
            cp16(st + rA * STRDH + cA, Ab + (size_t)rA * la + ko + cA);
#pragma unroll
        for (int j = 0; j < 2; j++)
            cp16(st + STGA_H + rWl[j] * STRDH + cWl[j], Wb + (size_t)wrW[j] * lw + ko + cWl[j]);
        asm volatile("cp.async.commit_group;\n");
    };

    const int npro = cpk < 2 ? cpk : 2;
    for (int s = 0; s < npro; s++) issue(cbase + s, s);

    for (int i = 0; i < cpk; i++) {
        const int rem = cpk - 1 - i;
        if (rem >= 1) asm volatile("cp.async.wait_group 1;\n");
        else          asm volatile("cp.async.wait_group 0;\n");
        __syncthreads();
        if (i + 2 < cpk) issue(cbase + i + 2, (i + 2) % 3);

        const __half* stg = smh + (i % 3) * STGF_H;
        const uint32_t* pA = (const uint32_t*)stg + (wm * 32 + g8) * 20 + tg;
        const uint32_t* pB = (const uint32_t*)(stg + STGA_H) + (wn * 32 + g8) * 20 + tg;
#pragma unroll
        for (int kk = 0; kk < 2; kk++) {
            const int ko = kk * 8;
            uint32_t a0[4], a1[4], b[4][2];
            a0[0] = pA[ko];               a0[1] = pA[8 * 20 + ko];
            a0[2] = pA[ko + 4];           a0[3] = pA[8 * 20 + ko + 4];
            a1[0] = pA[16 * 20 + ko];     a1[1] = pA[24 * 20 + ko];
            a1[2] = pA[16 * 20 + ko + 4]; a1[3] = pA[24 * 20 + ko + 4];
#pragma unroll
            for (int ni = 0; ni < 4; ni++) {
                b[ni][0] = pB[ni * 8 * 20 + ko];
                b[ni][1] = pB[ni * 8 * 20 + ko + 4];
            }
#pragma unroll
            for (int ni = 0; ni < 4; ni++) {
                mma16(acc[0][ni], a0, b[ni]);
                mma16(acc[1][ni], a1, b[ni]);
            }
        }
    }
}

__device__ __forceinline__ void store_partial(float acc[2][4][4], int wm, int wn, int g8, int tg) {
    float* pp = g_part + (size_t)blockIdx.x * 16384;
#pragma unroll
    for (int mi = 0; mi < 2; mi++)
#pragma unroll
        for (int ni = 0; ni < 4; ni++) {
            int r = wm * 32 + mi * 16 + g8, c = wn * 32 + ni * 8 + tg * 2;
            *(float2*)(pp + r * 256 + c)       = make_float2(acc[mi][ni][0], acc[mi][ni][1]);
            *(float2*)(pp + (r + 8) * 256 + c) = make_float2(acc[mi][ni][2], acc[mi][ni][3]);
        }
}

__device__ __forceinline__ void reduce_slice(float* red, int baseCta, int split, int sk, int rpc) {
    const float* pb = g_part + (size_t)baseCta * 16384 + sk * rpc * 256;
    for (int e4 = threadIdx.x; e4 < rpc * 64; e4 += NTHR) {
        float4 s = __ldcv((const float4*)(pb + e4 * 4));
        for (int p = 1; p < split; p++) {
            float4 v = __ldcv((const float4*)(pb + (size_t)p * 16384 + e4 * 4));
            s.x += v.x; s.y += v.y; s.z += v.z; s.w += v.w;
        }
        *(float4*)(red + e4 * 4) = s;
    }
    __syncthreads();
}

// ---------------- persistent megakernel ----------------
__global__ void __launch_bounds__(NTHR, 1) mega_kernel(
    const float* __restrict__ bi0, const float* __restrict__ bh0,
    const float* __restrict__ bi1, const float* __restrict__ bh1,
    float* __restrict__ outs, float* __restrict__ attns,
    float* __restrict__ hF, float* __restrict__ cF)
{
    extern __shared__ __align__(16) __half smh[];
    const int tid = threadIdx.x;
    const int w = tid >> 5, lane = tid & 31;
    const int wm = w >> 3, wn = w & 7;
    const int g8 = lane >> 2, tg = lane & 3;
    const int cta = blockIdx.x;

    float acc[2][4][4];

    // ---- startup A: g_pre = inp @ Wih0_left^T (all t) ----
    for (int tile = cta; tile < 64 * 16; tile += NCTA) {
        const int t = tile >> 4, grp = tile & 15;
        const int n0 = grp * 64;
        Seg s{g_inph + (size_t)t * B_ * E_, E_, g_wih0h, EH_, 16};
        gemm_ml(s, s, 16, 0, 1, n0, smh, acc, wm, wn, g8, tg);
        float* dst = g_pre + (size_t)t * B_ * 4 * H_;
#pragma unroll
        for (int mi = 0; mi < 2; mi++)
#pragma unroll
            for (int ni = 0; ni < 4; ni++) {
                int r = wm * 32 + mi * 16 + g8, cc = wn * 32 + ni * 8 + tg * 2;
                int n = (cc >> 6) * H_ + n0 + (cc & 63);
                *(float2*)(dst + (size_t)r * 4096 + n)       = make_float2(acc[mi][ni][0], acc[mi][ni][1]);
                *(float2*)(dst + (size_t)(r + 8) * 4096 + n) = make_float2(acc[mi][ni][2], acc[mi][ni][3]);
            }
    }

    // ---- startup C: g_ctxph = half(ctx_flat @ Wa) via transposed Wa ----
    for (int tile = cta; tile < 128 * 4; tile += NCTA) {
        const int rt = tile >> 2, grp = tile & 3;
        const int nb = grp * 256;
        const int flatbase = rt * 64;
        Seg s{g_ctxh + (size_t)flatbase * H_, H_, g_wat, H_, 32};
        gemm_ml(s, s, 32, 0, 0, nb, smh, acc, wm, wn, g8, tg);
#pragma unroll
        for (int mi = 0; mi < 2; mi++)
#pragma unroll
            for (int ni = 0; ni < 4; ni++) {
                int r = wm * 32 + mi * 16 + g8, cc = wn * 32 + ni * 8 + tg * 2;
                *(__half2*)(g_ctxph + (size_t)(flatbase + r) * H_ + nb + cc) =
                    __floats2half2_rn(acc[mi][ni][0], acc[mi][ni][1]);
                *(__half2*)(g_ctxph + (size_t)(flatbase + r + 8) * H_ + nb + cc) =
                    __floats2half2_rn(acc[mi][ni][2], acc[mi][ni][3]);
            }
    }
    arrive(&c_p4);   // startup counts as step -1 completion

    const int grpL = cta >> 3, skL = cta & 7;     // lstm: 16 grp x 8 split

    for (int t = 0; t < T_; t++) {
        const __half* fd  = t ? g_feedh : g_zerosh;
        const __half* h0p = g_hb0h + (size_t)(t & 1) * BH_;
        const __half* h1p = g_hb1h + (size_t)(t & 1) * BH_;
        __half* h0n = g_hb0h + (size_t)((t + 1) & 1) * BH_;
        __half* h1n = g_hb1h + (size_t)((t + 1) & 1) * BH_;
        float* red = (float*)smh;

        // ---- P0: lstm0 ----
        wait_ge(&c_p4, (unsigned long long)(t + 1) * NCTA);
        {
            const int n0 = grpL * 64;
            Seg s0{fd, H_, g_wih0h + E_, EH_, 32};
            Seg s1{h0p, H_, g_whh0h, H_, 32};
            gemm_ml(s0, s1, 8, skL * 8, 1, n0, smh, acc, wm, wn, g8, tg);
            store_partial(acc, wm, wn, g8, tg);
            arrive(&c_l0[grpL]);
            wait_ge(&c_l0[grpL], (unsigned long long)(t + 1) * 8);
            reduce_slice(red, grpL * 8, 8, skL, 8);
            const float* pre = g_pre + (size_t)t * B_ * 4 * H_;
            for (int e = tid; e < 8 * 64; e += NTHR) {
                int lm = e >> 6, j = e & 63;
                int m = skL * 8 + lm, n = n0 + j;
                float iv = red[lm * 256 + j]       + bi0[n]          + bh0[n]          + pre[(size_t)m * 4096 + n];
                float fv = red[lm * 256 + 64 + j]  + bi0[H_ + n]     + bh0[H_ + n]     + pre[(size_t)m * 4096 + H_ + n];
                float gv = red[lm * 256 + 128 + j] + bi0[2 * H_ + n] + bh0[2 * H_ + n] + pre[(size_t)m * 4096 + 2 * H_ + n];
                float ov = red[lm * 256 + 192 + j] + bi0[3 * H_ + n] + bh0[3 * H_ + n] + pre[(size_t)m * 4096 + 3 * H_ + n];
                float cp = g_cb0[(size_t)m * H_ + n];
                float c2 = sigf(fv) * cp + sigf(iv) * tanhf(gv);
                float h2 = sigf(ov) * tanhf(c2);
                g_cb0[(size_t)m * H_ + n]   = c2;
                g_hraw0[(size_t)m * H_ + n] = h2;
                h0n[(size_t)m * H_ + n] = __float2half_rn(h2);
            }
            arrive(&c_p0);
        }

        // ---- P1: lstm1 ----
        wait_ge(&c_p0, (unsigned long long)(t + 1) * NCTA);
        {
            const int n0 = grpL * 64;
            Seg s0{h0n, H_, g_wih1h, H_, 32};
            Seg s1{h1p, H_, g_whh1h, H_, 32};
            gemm_ml(s0, s1, 8, skL * 8, 1, n0, smh, acc, wm, wn, g8, tg);
            store_partial(acc, wm, wn, g8, tg);
            arrive(&c_l1[grpL]);
            wait_ge(&c_l1[grpL], (unsigned long long)(t + 1) * 8);
            reduce_slice(red, grpL * 8, 8, skL, 8);
            for (int e = tid; e < 8 * 64; e += NTHR) {
                int lm = e >> 6, j = e & 63;
                int m = skL * 8 + lm, n = n0 + j;
                float iv = red[lm * 256 + j]       + bi1[n]          + bh1[n];
                float fv = red[lm * 256 + 64 + j]  + bi1[H_ + n]     + bh1[H_ + n];
                float gv = red[lm * 256 + 128 + j] + bi1[2 * H_ + n] + bh1[2 * H_ + n];
                float ov = red[lm * 256 + 192 + j] + bi1[3 * H_ + n] + bh1[3 * H_ + n];
                float cp = g_cb1[(size_t)m * H_ + n];
                float c2 = sigf(fv) * cp + sigf(iv) * tanhf(gv);
                float h2 = sigf(ov) * tanhf(c2);
                g_cb1[(size_t)m * H_ + n]   = c2;
                g_hraw1[(size_t)m * H_ + n] = h2;
                h1n[(size_t)m * H_ + n] = __float2half_rn(h2);
            }
            arrive(&c_p1);
        }

        // ---- P3: attention (CTAs 0..63, CTA-local via ctxph) || oh1 (CTAs 64..127) ----
        wait_ge(&c_p1, (unsigned long long)(t + 1) * NCTA);
        if (cta < 64) {
            const int b = cta;
            float* qs   = (float*)smh;
            float* sc   = qs + H_;
            float* sal  = sc + S_;
            float* red8 = sal + S_;
            __syncthreads();   // smem reuse
            {
                __half2 hv = __ldcv((const __half2*)(h1n + (size_t)b * H_) + tid);
                float2 f = __half22float2(hv);
                qs[tid * 2]     = f.x;
                qs[tid * 2 + 1] = f.y;
            }
            __syncthreads();
            // scores: 16 warps x 8 s = 128, reading precomputed ctxp (plain loads, L1-friendly)
#pragma unroll
            for (int i = 0; i < 8; i++) {
                const int s = w * 8 + i;
                const uint4* row = (const uint4*)(g_ctxph + ((size_t)s * B_ + b) * H_);
                float a2 = 0.f;
#pragma unroll
                for (int j = 0; j < 4; j++) {
                    uint4 cv = row[j * 32 + lane];
                    const float* qp = qs + j * 256 + lane * 8;
                    float2 c0 = __half22float2(*(const __half2*)&cv.x);
                    float2 c1 = __half22float2(*(const __half2*)&cv.y);
                    float2 c2 = __half22float2(*(const __half2*)&cv.z);
                    float2 c3 = __half22float2(*(const __half2*)&cv.w);
                    a2 += qp[0] * c0.x + qp[1] * c0.y + qp[2] * c1.x + qp[3] * c1.y
                        + qp[4] * c2.x + qp[5] * c2.y + qp[6] * c3.x + qp[7] * c3.y;
                }
#pragma unroll
                for (int o = 16; o > 0; o >>= 1) a2 += __shfl_xor_sync(0xFFFFFFFFu, a2, o);
                if (!lane) sc[s] = a2;
            }
            __syncthreads();
            float mx = -3.4e38f;
            if (tid < 128) mx = sc[tid];
#pragma unroll
            for (int o = 16; o > 0; o >>= 1) mx = fmaxf(mx, __shfl_xor_sync(0xFFFFFFFFu, mx, o));
            if (tid < 128 && !lane) red8[w] = mx;
            __syncthreads();
            const float gmx = fmaxf(fmaxf(red8[0], red8[1]), fmaxf(red8[2], red8[3]));
            float e = 0.f;
            if (tid < 128) { e = expf(sc[tid] - gmx); sal[tid] = e; }
            float se = e;
#pragma unroll
            for (int o = 16; o > 0; o >>= 1) se += __shfl_xor_sync(0xFFFFFFFFu, se, o);
            if (tid < 128 && !lane) red8[4 + w] = se;
            __syncthreads();
            const float inv = 1.f / (red8[4] + red8[5] + red8[6] + red8[7]);
            if (tid < 128) {
                float a = sal[tid] * inv;
                sal[tid] = a;
                attns[(size_t)t * B_ * S_ + b * S_ + tid] = a;
            }
            __syncthreads();
            // cvec: 512 threads x 2 dims
            const int d0 = tid * 2;
            float2 a2 = make_float2(0.f, 0.f);
#pragma unroll 8
            for (int s = 0; s < S_; s++) {
                const float a = sal[s];
                float2 c = __half22float2(*(const __half2*)(g_ctxh + ((size_t)s * B_ + b) * H_ + d0));
                a2.x += a * c.x;
                a2.y += a * c.y;
            }
            *(__half2*)(g_cvech + (size_t)b * H_ + d0) = __floats2half2_rn(a2.x, a2.y);
            arrive(&c_p3);
        } else {
            // oh1 = h1 @ WoutR^T (4 grp x 16 split, cpk=2)
            const int sub = cta - 64;
            const int grpO = sub >> 4, skO = sub & 15;
            const int nb = grpO * 256;
            Seg s0{h1n, H_, g_wouth + H_, 2 * H_, 32};
            gemm_ml(s0, s0, 2, skO * 2, 0, nb, smh, acc, wm, wn, g8, tg);
            store_partial(acc, wm, wn, g8, tg);
            arrive(&c_oh[grpO]);
            wait_ge(&c_oh[grpO], (unsigned long long)(t + 1) * 16);
            reduce_slice(red, 64 + grpO * 16, 16, skO, 4);
            for (int e = tid; e < 4 * 256; e += NTHR) {
                int lm = e >> 8, c = e & 255;
                int m = skO * 4 + lm;
                g_oh1[(size_t)m * H_ + nb + c] = red[e];
            }
            arrive(&c_p3);
        }

        // ---- P4: cvproj = tanh(cvec @ WoutL^T + oh1) (4 grp x 32 split, cpk=1) ----
        wait_ge(&c_p3, (unsigned long long)(t + 1) * NCTA);
        {
            const int grpC = cta >> 5, skC = cta & 31;
            const int nb = grpC * 256;
            Seg s0{g_cvech, H_, g_wouth, 2 * H_, 32};
            gemm_ml(s0, s0, 1, skC, 0, nb, smh, acc, wm, wn, g8, tg);
            store_partial(acc, wm, wn, g8, tg);
            arrive(&c_cv[grpC]);
            wait_ge(&c_cv[grpC], (unsigned long long)(t + 1) * 32);
            reduce_slice(red, grpC * 32, 32, skC, 2);
            for (int e = tid; e < 2 * 256; e += NTHR) {
                int lm = e >> 8, c = e & 255;
                int m = skC * 2 + lm;
                float v = tanhf(red[e] + __ldcv(g_oh1 + (size_t)m * H_ + nb + c));
                outs[(size_t)t * B_ * H_ + (size_t)m * H_ + nb + c] = v;
                g_feedh[(size_t)m * H_ + nb + c] = __float2half_rn(v);
            }
            arrive(&c_p4);
        }
    }

    // ---- finalize ----
    wait_ge(&c_p4, (unsigned long long)(T_ + 1) * NCTA);
    {
        const int i = cta * NTHR + tid;   // exactly BH_
        hF[i]       = __ldcv(g_hraw0 + i);
        hF[BH_ + i] = __ldcv(g_hraw1 + i);
        cF[i]       = __ldcv(g_cb0 + i);
        cF[BH_ + i] = __ldcv(g_cb1 + i);
    }
}

// ---------------- host launcher ----------------
extern "C" void kernel_launch(void* const* d_in, const int* in_sizes, int n_in,
                              void* d_out, int out_size) {
    const float* inp   = (const float*)d_in[0];
    const float* ctx   = (const float*)d_in[1];
    const float* h0in  = (const float*)d_in[2];
    const float* c0in  = (const float*)d_in[3];
    const float* W_ih0 = (const float*)d_in[4];
    const float* b_ih0 = (const float*)d_in[5];
    const float* W_hh0 = (const float*)d_in[6];
    const float* b_hh0 = (const float*)d_in[7];
    const float* W_ih1 = (const float*)d_in[8];
    const float* b_ih1 = (const float*)d_in[9];
    const float* W_hh1 = (const float*)d_in[10];
    const float* b_hh1 = (const float*)d_in[11];
    const float* W_a   = (const float*)d_in[12];
    const float* W_out = (const float*)d_in[13];

    float* out   = (float*)d_out;
    float* outs  = out;                 // (T,B,H)
    float* hF    = out + TBH_;          // (2,B,H)
    float* cF    = hF + 2 * BH_;        // (2,B,H)
    float* attns = cF + 2 * BH_;        // (T,B,S)

    const int smemB = NSTG_ * STGF_H * sizeof(__half);   // 76800
    static int attrSet = 0;
    if (!attrSet) {
        cudaFuncSetAttribute(mega_kernel, cudaFuncAttributeMaxDynamicSharedMemorySize, smemB);
        attrSet = 1;
    }

    prep_weights<<<2048, 512>>>(W_ih0, W_hh0, W_ih1, W_hh1, W_out);
    prep_transpose<<<dim3(H_ / 32, H_ / 32), 256>>>(W_a);
    prep_state<<<2048, 512>>>(inp, ctx, h0in, c0in);
    mega_kernel<<<NCTA, NTHR, smemB>>>(b_ih0, b_hh0, b_ih1, b_hh1, outs, attns, hF, cF);
}